// round 10
// baseline (speedup 1.0000x reference)
#include <cuda_runtime.h>
#include <cuda_bf16.h>
#include <math.h>
#include <stdint.h>

#define T_SEQ 128
#define BATCH 64
#define EMB   2048
#define HID   2048
#define VOCAB 10000
#define MB_   (T_SEQ * BATCH)   /* 8192 */
#define BH    (BATCH * HID)     /* 131072 */

/* ------------------------------------------------------------------ */
/* Scratch (device globals only)                                       */
/* ------------------------------------------------------------------ */
__device__ float g_X0[(size_t)MB_ * HID];
__device__ float g_X1[(size_t)MB_ * HID];
__device__ float g_part[8][BH];
__device__ int   g_cnt[32];
__device__ int   g_is64;

__device__ __nv_bfloat16 g_emb_hi [(size_t)VOCAB * EMB];
__device__ __nv_bfloat16 g_emb_lo [(size_t)VOCAB * EMB];
__device__ __nv_bfloat16 g_w0x_hi [(size_t)HID * HID];
__device__ __nv_bfloat16 g_w0x_lo [(size_t)HID * HID];
__device__ __nv_bfloat16 g_w0h_hi [(size_t)HID * HID];
__device__ __nv_bfloat16 g_w0h_lo [(size_t)HID * HID];
__device__ __nv_bfloat16 g_w1x_hi [(size_t)HID * HID];
__device__ __nv_bfloat16 g_w1x_lo [(size_t)HID * HID];
__device__ __nv_bfloat16 g_w1h_hi [(size_t)HID * HID];
__device__ __nv_bfloat16 g_w1h_lo [(size_t)HID * HID];
__device__ __nv_bfloat16 g_wout_hi[(size_t)VOCAB * HID];
__device__ __nv_bfloat16 g_wout_lo[(size_t)VOCAB * HID];
__device__ __nv_bfloat16 g_H0_hi  [(size_t)MB_ * HID];
__device__ __nv_bfloat16 g_H0_lo  [(size_t)MB_ * HID];
__device__ __nv_bfloat16 g_H1_hi  [(size_t)MB_ * HID];
__device__ __nv_bfloat16 g_H1_lo  [(size_t)MB_ * HID];
__device__ __nv_bfloat16 g_hin_hi [2 * BH];
__device__ __nv_bfloat16 g_hin_lo [2 * BH];

/* ------------------------------------------------------------------ */
__device__ __forceinline__ uint32_t s2u(const void* p) {
    uint32_t a;
    asm("{ .reg .u64 t; cvta.to.shared.u64 t, %1; cvt.u32.u64 %0, t; }"
        : "=r"(a) : "l"(p));
    return a;
}
__device__ __forceinline__ void ldm_x4(uint32_t& r0, uint32_t& r1,
                                       uint32_t& r2, uint32_t& r3, uint32_t a) {
    asm volatile("ldmatrix.sync.aligned.m8n8.x4.shared.b16 {%0,%1,%2,%3}, [%4];"
                 : "=r"(r0), "=r"(r1), "=r"(r2), "=r"(r3) : "r"(a));
}
__device__ __forceinline__ void mma16816(float* c, const uint32_t* a,
                                         const uint32_t* b) {
    asm volatile(
        "mma.sync.aligned.m16n8k16.row.col.f32.bf16.bf16.f32 "
        "{%0,%1,%2,%3}, {%4,%5,%6,%7}, {%8,%9}, {%0,%1,%2,%3};"
        : "+f"(c[0]), "+f"(c[1]), "+f"(c[2]), "+f"(c[3])
        : "r"(a[0]), "r"(a[1]), "r"(a[2]), "r"(a[3]), "r"(b[0]), "r"(b[1]));
}
__device__ __forceinline__ void cpa16(uint32_t dst, const void* src, int srcsz) {
    asm volatile("cp.async.cg.shared.global [%0], [%1], 16, %2;"
                 :: "r"(dst), "l"(src), "r"(srcsz) : "memory");
}
__device__ __forceinline__ void cpa_commit() {
    asm volatile("cp.async.commit_group;" ::: "memory");
}

/* ------------------------------------------------------------------ */
__global__ void detect_idx_kernel(const unsigned int* __restrict__ p) {
    if (threadIdx.x == 0) {
        unsigned int o = 0;
#pragma unroll
        for (int i = 0; i < 16; i++) o |= p[2 * i + 1];
        g_is64 = (o == 0u) ? 1 : 0;
    }
}

/* ------------------------------------------------------------------ */
/* fp32 -> bf16 hi/lo split                                            */
/* ------------------------------------------------------------------ */
__global__ void conv_split(const float4* __restrict__ src, long n4,
                           int c4s, int ld4s,
                           __nv_bfloat162* __restrict__ hi,
                           __nv_bfloat162* __restrict__ lo)
{
    long i = (long)blockIdx.x * 256 + threadIdx.x;
    if (i >= n4) return;
    long r = i >> c4s;
    long c = i & ((1L << c4s) - 1);
    float4 v = src[(r << ld4s) + c];
    __nv_bfloat16 hx = __float2bfloat16(v.x), hy = __float2bfloat16(v.y);
    __nv_bfloat16 hz = __float2bfloat16(v.z), hw = __float2bfloat16(v.w);
    __nv_bfloat162 h0; h0.x = hx; h0.y = hy;
    __nv_bfloat162 h1; h1.x = hz; h1.y = hw;
    hi[2 * i] = h0; hi[2 * i + 1] = h1;
    __nv_bfloat162 l0, l1;
    l0.x = __float2bfloat16(v.x - __bfloat162float(hx));
    l0.y = __float2bfloat16(v.y - __bfloat162float(hy));
    l1.x = __float2bfloat16(v.z - __bfloat162float(hz));
    l1.y = __float2bfloat16(v.w - __bfloat162float(hw));
    lo[2 * i] = l0; lo[2 * i + 1] = l1;
}

/* ------------------------------------------------------------------ */
/* Big mma.sync bf16 3-pass GEMM, 512 threads (16 warps, 4/SMSP),      */
/* 4-stage cp.async pipeline:  C[M,N] = A[M,K=2048]*B[N,K]^T + bias    */
/* Warp layout 4m x 4n, warp tile 32x32.                               */
/* ------------------------------------------------------------------ */
#define ROWB   80
#define R_AHI  0
#define R_ALO  10240
#define R_BHI  20480
#define R_BLO  30720
#define STAGEB 40960
#define NSTG   4
#define GEMM_SMEM (NSTG * STAGEB)   /* 160 KB */

__global__ __launch_bounds__(512, 1) void gemm_mma(
    const __nv_bfloat16* __restrict__ Ahi, const __nv_bfloat16* __restrict__ Alo,
    const void* __restrict__ aidx,
    const __nv_bfloat16* __restrict__ Bhi, const __nv_bfloat16* __restrict__ Blo,
    int nrowsB, const float* __restrict__ bias,
    float* __restrict__ C, int ldc, int ncols)
{
    extern __shared__ char smem[];
    const uint32_t smbase = s2u(smem);

    const int tid  = threadIdx.x;
    const int lane = tid & 31;
    const int wid  = tid >> 5;
    const int wm   = wid & 3;          /* 4 m-groups of 32 rows */
    const int wn   = wid >> 2;         /* 4 n-groups of 32 cols */
    const int bm   = blockIdx.y * 128;
    const int bn   = blockIdx.x * 128;

    /* loaders: 4 threads per row, one 16B chunk each, per array */
    const int lrow = tid >> 2;         /* 0..127 */
    const int c16  = tid & 3;          /* chunk 0..3 (16B each)  */
    const uint32_t dstOff = (uint32_t)(lrow * ROWB + c16 * 16);

    size_t aoff;
    {
        const int m = bm + lrow;
        size_t row;
        if (aidx) {
            if (g_is64) row = (size_t)((const long long*)aidx)[m];
            else        row = (size_t)((const int*)aidx)[m];
        } else row = (size_t)m;
        aoff = row * 2048 + (size_t)c16 * 8;
    }
    const int  nrow = bn + lrow;
    const int  bsz  = (nrow < nrowsB) ? 16 : 0;
    const size_t boff = (size_t)((nrow < nrowsB) ? nrow : 0) * 2048
                      + (size_t)c16 * 8;

    const int rlane  = lane & 15;
    const int khalf2 = (lane >> 4) * 16;
    uint32_t rowA[2], rowB[2];
#pragma unroll
    for (int mt = 0; mt < 2; mt++)
        rowA[mt] = (uint32_t)((wm * 32 + mt * 16 + rlane) * ROWB);
#pragma unroll
    for (int nt = 0; nt < 2; nt++)
        rowB[nt] = (uint32_t)((wn * 32 + nt * 16 + rlane) * ROWB);

    float acc[2][4][4];
#pragma unroll
    for (int mt = 0; mt < 2; mt++)
#pragma unroll
        for (int j = 0; j < 4; j++)
#pragma unroll
            for (int q = 0; q < 4; q++) acc[mt][j][q] = 0.f;

    const int NIT = 2048 / 32;   /* 64 */

    auto issue = [&](int it) {
        const uint32_t sb = smbase + (uint32_t)(it & (NSTG - 1)) * STAGEB;
        const size_t kb = (size_t)it * 32;
        cpa16(sb + R_AHI + dstOff, Ahi + aoff + kb, 16);
        cpa16(sb + R_ALO + dstOff, Alo + aoff + kb, 16);
        cpa16(sb + R_BHI + dstOff, Bhi + boff + kb, bsz);
        cpa16(sb + R_BLO + dstOff, Blo + boff + kb, bsz);
        cpa_commit();
    };

    issue(0); issue(1); issue(2);

    for (int it = 0; it < NIT; it++) {
        asm volatile("cp.async.wait_group 2;" ::: "memory");
        __syncthreads();
        if (it + NSTG - 1 < NIT) issue(it + NSTG - 1);
        else                     cpa_commit();

        const uint32_t sb = smbase + (uint32_t)(it & (NSTG - 1)) * STAGEB;
#pragma unroll
        for (int kk = 0; kk < 2; kk++) {
            const uint32_t kbyt = (uint32_t)(kk * 32 + khalf2);
            uint32_t ah[2][4], al[2][4];
#pragma unroll
            for (int mt = 0; mt < 2; mt++) {
                ldm_x4(ah[mt][0], ah[mt][1], ah[mt][2], ah[mt][3],
                       sb + R_AHI + rowA[mt] + kbyt);
                ldm_x4(al[mt][0], al[mt][1], al[mt][2], al[mt][3],
                       sb + R_ALO + rowA[mt] + kbyt);
            }
            uint32_t bh[4][2], bl[4][2];
#pragma unroll
            for (int nt = 0; nt < 2; nt++) {
                uint32_t t0, t1, t2, t3;
                ldm_x4(t0, t1, t2, t3, sb + R_BHI + rowB[nt] + kbyt);
                bh[2*nt][0] = t0; bh[2*nt][1] = t2;
                bh[2*nt+1][0] = t1; bh[2*nt+1][1] = t3;
                ldm_x4(t0, t1, t2, t3, sb + R_BLO + rowB[nt] + kbyt);
                bl[2*nt][0] = t0; bl[2*nt][1] = t2;
                bl[2*nt+1][0] = t1; bl[2*nt+1][1] = t3;
            }
#pragma unroll
            for (int mt = 0; mt < 2; mt++)
#pragma unroll
                for (int j = 0; j < 4; j++) {
                    mma16816(acc[mt][j], ah[mt], bh[j]);
                    mma16816(acc[mt][j], ah[mt], bl[j]);
                    mma16816(acc[mt][j], al[mt], bh[j]);
                }
        }
    }

    const int gid = lane >> 2;
    const int tig = lane & 3;
#pragma unroll
    for (int mt = 0; mt < 2; mt++) {
#pragma unroll
        for (int j = 0; j < 4; j++) {
            const int col = bn + wn * 32 + j * 8 + tig * 2;
            if (col < ncols) {
                const float bx = bias[col], by = bias[col + 1];
                const size_t r0 = (size_t)(bm + wm * 32 + mt * 16 + gid);
                const size_t r1 = r0 + 8;
                float2 v0 = make_float2(acc[mt][j][0] + bx, acc[mt][j][1] + by);
                float2 v1 = make_float2(acc[mt][j][2] + bx, acc[mt][j][3] + by);
                *(float2*)(C + r0 * (size_t)ldc + col) = v0;
                *(float2*)(C + r1 * (size_t)ldc + col) = v1;
            }
        }
    }
}

/* ------------------------------------------------------------------ */
/* Recurrent step on mma.sync bf16 3-pass, 3-stage pipeline            */
/* (unchanged from R9).                                                */
/* ------------------------------------------------------------------ */
#define SROWB  144
#define R2_AH  0
#define R2_AL  9216
#define R2_BH  18432
#define R2_BL  27648
#define STAGE2 36864
#define STEP_SMEM (3 * STAGE2)   /* 108 KB */

__global__ __launch_bounds__(256, 1) void rnn_step_mma(
    const __nv_bfloat16* __restrict__ Ahi, const __nv_bfloat16* __restrict__ Alo,
    const __nv_bfloat16* __restrict__ Whi, const __nv_bfloat16* __restrict__ Wlo,
    const float* __restrict__ Xadd, float* __restrict__ part,
    __nv_bfloat162* __restrict__ outHi, __nv_bfloat162* __restrict__ outLo)
{
    extern __shared__ char smem[];
    __shared__ int s_last;
    const uint32_t smbase = s2u(smem);

    const int tid  = threadIdx.x;
    const int lane = tid & 31;
    const int wid  = tid >> 5;
    const int wm   = wid & 3;
    const int wn   = wid >> 2;
    const int strip  = blockIdx.x;
    const int kslice = blockIdx.y;
    const int kbase0 = kslice * 256;

    const int lrow = tid >> 2;
    const int c0   = (tid & 3) * 2;
    const uint32_t dOff = (uint32_t)(lrow * SROWB + c0 * 16);
    const size_t aO = (size_t)lrow * 2048 + (size_t)c0 * 8;
    const size_t bO = (size_t)(strip * 64 + lrow) * 2048 + (size_t)c0 * 8;

    auto issue = [&](int it) {
        const uint32_t sb = smbase + (uint32_t)(it % 3) * STAGE2;
        const size_t kb = (size_t)(kbase0 + it * 64);
        cpa16(sb + R2_AH + dOff,      Ahi + aO + kb,     16);
        cpa16(sb + R2_AH + dOff + 16, Ahi + aO + kb + 8, 16);
        cpa16(sb + R2_AL + dOff,      Alo + aO + kb,     16);
        cpa16(sb + R2_AL + dOff + 16, Alo + aO + kb + 8, 16);
        cpa16(sb + R2_BH + dOff,      Whi + bO + kb,     16);
        cpa16(sb + R2_BH + dOff + 16, Whi + bO + kb + 8, 16);
        cpa16(sb + R2_BL + dOff,      Wlo + bO + kb,     16);
        cpa16(sb + R2_BL + dOff + 16, Wlo + bO + kb + 8, 16);
        cpa_commit();
    };

    const int rlane = lane & 15;
    const int khalf = (lane >> 4) * 16;
    const uint32_t arow = (uint32_t)((wm * 16 + rlane) * SROWB);
    uint32_t brow[2];
    brow[0] = (uint32_t)((wn * 32 + rlane) * SROWB);
    brow[1] = (uint32_t)((wn * 32 + 16 + rlane) * SROWB);

    float acc[4][4];
#pragma unroll
    for (int j = 0; j < 4; j++)
#pragma unroll
        for (int q = 0; q < 4; q++) acc[j][q] = 0.f;

    issue(0); issue(1);

    for (int it = 0; it < 4; it++) {
        asm volatile("cp.async.wait_group 1;" ::: "memory");
        __syncthreads();
        if (it + 2 < 4) issue(it + 2);
        else            cpa_commit();

        const uint32_t sb = smbase + (uint32_t)(it % 3) * STAGE2;
#pragma unroll
        for (int kk = 0; kk < 4; kk++) {
            const uint32_t kbyt = (uint32_t)(kk * 32 + khalf);
            uint32_t ah[4], al[4];
            ldm_x4(ah[0], ah[1], ah[2], ah[3], sb + R2_AH + arow + kbyt);
            ldm_x4(al[0], al[1], al[2], al[3], sb + R2_AL + arow + kbyt);
            uint32_t bh[4][2], bl[4][2];
#pragma unroll
            for (int nt = 0; nt < 2; nt++) {
                uint32_t t0, t1, t2, t3;
                ldm_x4(t0, t1, t2, t3, sb + R2_BH + brow[nt] + kbyt);
                bh[2*nt][0] = t0; bh[2*nt][1] = t2;
                bh[2*nt+1][0] = t1; bh[2*nt+1][1] = t3;
                ldm_x4(t0, t1, t2, t3, sb + R2_BL + brow[nt] + kbyt);
                bl[2*nt][0] = t0; bl[2*nt][1] = t2;
                bl[2*nt+1][0] = t1; bl[2*nt+1][1] = t3;
            }
#pragma unroll
            for (int j = 0; j < 4; j++) {
                mma16816(acc[j], ah, bh[j]);
                mma16816(acc[j], ah, bl[j]);
                mma16816(acc[j], al, bh[j]);
            }
        }
    }

    float* dst = part + (size_t)kslice * BH;
    const int r0 = wm * 16 + (lane >> 2);
#pragma unroll
    for (int j = 0; j < 4; j++) {
        const int col = strip * 64 + wn * 32 + j * 8 + (lane & 3) * 2;
        *(float2*)(dst + (size_t)r0 * 2048 + col) =
            make_float2(acc[j][0], acc[j][1]);
        *(float2*)(dst + (size_t)(r0 + 8) * 2048 + col) =
            make_float2(acc[j][2], acc[j][3]);
    }

    __threadfence();
    if (tid == 0) {
        int old = atomicAdd(&g_cnt[strip], 1);
        s_last = (old == 7) ? 1 : 0;
    }
    __syncthreads();
    if (!s_last) return;
    __threadfence();

    const float4* p4 = (const float4*)part;
    const float4* x4 = (const float4*)Xadd;
    for (int u = tid; u < 1024; u += 256) {
        const int m  = u >> 4;
        const int c4 = u & 15;
        const size_t off = (size_t)m * 512 + (size_t)strip * 16 + c4;
        float4 sv = p4[off];
#pragma unroll
        for (int kg = 1; kg < 8; kg++) {
            float4 p = p4[(size_t)kg * (BH / 4) + off];
            sv.x += p.x; sv.y += p.y; sv.z += p.z; sv.w += p.w;
        }
        float4 xv = x4[off];
        sv.x = tanhf(sv.x + xv.x); sv.y = tanhf(sv.y + xv.y);
        sv.z = tanhf(sv.z + xv.z); sv.w = tanhf(sv.w + xv.w);

        __nv_bfloat16 hx = __float2bfloat16(sv.x), hy = __float2bfloat16(sv.y);
        __nv_bfloat16 hz = __float2bfloat16(sv.z), hw = __float2bfloat16(sv.w);
        __nv_bfloat162 a; a.x = hx; a.y = hy;
        __nv_bfloat162 b; b.x = hz; b.y = hw;
        outHi[2 * off] = a; outHi[2 * off + 1] = b;
        __nv_bfloat162 la, lb;
        la.x = __float2bfloat16(sv.x - __bfloat162float(hx));
        la.y = __float2bfloat16(sv.y - __bfloat162float(hy));
        lb.x = __float2bfloat16(sv.z - __bfloat162float(hz));
        lb.y = __float2bfloat16(sv.w - __bfloat162float(hw));
        outLo[2 * off] = la; outLo[2 * off + 1] = lb;
    }
    __threadfence();
    __syncthreads();
    if (tid == 0) g_cnt[strip] = 0;
}

/* ------------------------------------------------------------------ */
__global__ void copy_final_hl(
    const __nv_bfloat162* __restrict__ h0h, const __nv_bfloat162* __restrict__ h0l,
    const __nv_bfloat162* __restrict__ h1h, const __nv_bfloat162* __restrict__ h1l,
    float2* __restrict__ out)
{
    const int i = blockIdx.x * 256 + threadIdx.x;
    if (i >= BH) return;
    const __nv_bfloat162 h = (i < BH / 2) ? h0h[i] : h1h[i - BH / 2];
    const __nv_bfloat162 l = (i < BH / 2) ? h0l[i] : h1l[i - BH / 2];
    float2 v;
    v.x = __bfloat162float(h.x) + __bfloat162float(l.x);
    v.y = __bfloat162float(h.y) + __bfloat162float(l.y);
    out[i] = v;
}

/* ------------------------------------------------------------------ */
extern "C" void kernel_launch(void* const* d_in, const int* in_sizes, int n_in,
                              void* d_out, int out_size)
{
    (void)in_sizes; (void)n_in; (void)out_size;

    const void*  inputs = d_in[0];
    const float* hidden = (const float*)d_in[1];
    const float* emb    = (const float*)d_in[2];
    const float* W0     = (const float*)d_in[3];
    const float* b0     = (const float*)d_in[4];
    const float* W1     = (const float*)d_in[5];
    const float* b1     = (const float*)d_in[6];
    const float* Wout   = (const float*)d_in[7];
    const float* bout   = (const float*)d_in[8];
    float* out = (float*)d_out;

    float *pX0, *pX1, *pPart;
    __nv_bfloat16 *pEh, *pEl, *pW0xh, *pW0xl, *pW0hh, *pW0hl;
    __nv_bfloat16 *pW1xh, *pW1xl, *pW1hh, *pW1hl, *pWoh, *pWol;
    __nv_bfloat16 *pH0h, *pH0l, *pH1h, *pH1l, *pHIh, *pHIl;
    cudaGetSymbolAddress((void**)&pX0,   g_X0);
    cudaGetSymbolAddress((void**)&pX1,   g_X1);
    cudaGetSymbolAddress((void**)&pPart, g_part);
    cudaGetSymbolAddress((void**)&pEh,   g_emb_hi);
    cudaGetSymbolAddress((void**)&pEl,   g_emb_lo);
    cudaGetSymbolAddress((void**)&pW0xh, g_w0x_hi);
    cudaGetSymbolAddress((void**)&pW0xl, g_w0x_lo);
    cudaGetSymbolAddress((void**)&pW0hh, g_w0h_hi);
    cudaGetSymbolAddress((void**)&pW0hl, g_w0h_lo);
    cudaGetSymbolAddress((void**)&pW1xh, g_w1x_hi);
    cudaGetSymbolAddress((void**)&pW1xl, g_w1x_lo);
    cudaGetSymbolAddress((void**)&pW1hh, g_w1h_hi);
    cudaGetSymbolAddress((void**)&pW1hl, g_w1h_lo);
    cudaGetSymbolAddress((void**)&pWoh,  g_wout_hi);
    cudaGetSymbolAddress((void**)&pWol,  g_wout_lo);
    cudaGetSymbolAddress((void**)&pH0h,  g_H0_hi);
    cudaGetSymbolAddress((void**)&pH0l,  g_H0_lo);
    cudaGetSymbolAddress((void**)&pH1h,  g_H1_hi);
    cudaGetSymbolAddress((void**)&pH1l,  g_H1_lo);
    cudaGetSymbolAddress((void**)&pHIh,  g_hin_hi);
    cudaGetSymbolAddress((void**)&pHIl,  g_hin_lo);

    static int smem_set = 0;
    if (!smem_set) {
        cudaFuncSetAttribute(gemm_mma, cudaFuncAttributeMaxDynamicSharedMemorySize,
                             GEMM_SMEM);
        cudaFuncSetAttribute(rnn_step_mma, cudaFuncAttributeMaxDynamicSharedMemorySize,
                             STEP_SMEM);
        smem_set = 1;
    }

    detect_idx_kernel<<<1, 32>>>((const unsigned int*)inputs);

    /* hi/lo conversions */
    {
        long n4;
        n4 = (long)VOCAB * (EMB / 4);
        conv_split<<<(unsigned)((n4 + 255) / 256), 256>>>(
            (const float4*)emb, n4, 9, 9, (__nv_bfloat162*)pEh, (__nv_bfloat162*)pEl);
        n4 = (long)VOCAB * (HID / 4);
        conv_split<<<(unsigned)((n4 + 255) / 256), 256>>>(
            (const float4*)Wout, n4, 9, 9, (__nv_bfloat162*)pWoh, (__nv_bfloat162*)pWol);
        n4 = (long)HID * (HID / 4);
        conv_split<<<(unsigned)((n4 + 255) / 256), 256>>>(
            (const float4*)W0, n4, 9, 10,
            (__nv_bfloat162*)pW0xh, (__nv_bfloat162*)pW0xl);
        conv_split<<<(unsigned)((n4 + 255) / 256), 256>>>(
            (const float4*)(W0 + 2048), n4, 9, 10,
            (__nv_bfloat162*)pW0hh, (__nv_bfloat162*)pW0hl);
        conv_split<<<(unsigned)((n4 + 255) / 256), 256>>>(
            (const float4*)W1, n4, 9, 10,
            (__nv_bfloat162*)pW1xh, (__nv_bfloat162*)pW1xl);
        conv_split<<<(unsigned)((n4 + 255) / 256), 256>>>(
            (const float4*)(W1 + 2048), n4, 9, 10,
            (__nv_bfloat162*)pW1hh, (__nv_bfloat162*)pW1hl);
        n4 = (long)(2 * BH) / 4;
        conv_split<<<(unsigned)((n4 + 255) / 256), 256>>>(
            (const float4*)hidden, n4, 9, 9,
            (__nv_bfloat162*)pHIh, (__nv_bfloat162*)pHIl);
    }

    /* X0 = emb[inputs] @ W0x^T + b0 */
    {
        dim3 g(HID / 128, MB_ / 128);
        gemm_mma<<<g, 512, GEMM_SMEM>>>(pEh, pEl, inputs,
                                        pW0xh, pW0xl, HID, b0, pX0, HID, HID);
    }

    const dim3 gs(32, 8);

    /* layer-0 recurrence */
    for (int t = 0; t < T_SEQ; t++) {
        const __nv_bfloat16* ah = t ? (pH0h + (size_t)(t - 1) * BH) : pHIh;
        const __nv_bfloat16* al = t ? (pH0l + (size_t)(t - 1) * BH) : pHIl;
        rnn_step_mma<<<gs, 256, STEP_SMEM>>>(
            ah, al, pW0hh, pW0hl, pX0 + (size_t)t * BH, pPart,
            (__nv_bfloat162*)(pH0h + (size_t)t * BH),
            (__nv_bfloat162*)(pH0l + (size_t)t * BH));
    }

    /* X1 = H0 @ W1x^T + b1 */
    {
        dim3 g(HID / 128, MB_ / 128);
        gemm_mma<<<g, 512, GEMM_SMEM>>>(pH0h, pH0l, (const void*)0,
                                        pW1xh, pW1xl, HID, b1, pX1, HID, HID);
    }

    /* layer-1 recurrence */
    for (int t = 0; t < T_SEQ; t++) {
        const __nv_bfloat16* ah = t ? (pH1h + (size_t)(t - 1) * BH) : (pHIh + BH);
        const __nv_bfloat16* al = t ? (pH1l + (size_t)(t - 1) * BH) : (pHIl + BH);
        rnn_step_mma<<<gs, 256, STEP_SMEM>>>(
            ah, al, pW1hh, pW1hl, pX1 + (size_t)t * BH, pPart,
            (__nv_bfloat162*)(pH1h + (size_t)t * BH),
            (__nv_bfloat162*)(pH1l + (size_t)t * BH));
    }

    /* logits = H1 @ Wout^T + bout */
    {
        dim3 g((VOCAB + 127) / 128, MB_ / 128);
        gemm_mma<<<g, 512, GEMM_SMEM>>>(pH1h, pH1l, (const void*)0,
                                        pWoh, pWol, VOCAB, bout, out, VOCAB, VOCAB);
    }

    copy_final_hl<<<(BH + 255) / 256, 256>>>(
        (const __nv_bfloat162*)(pH0h + (size_t)(T_SEQ - 1) * BH),
        (const __nv_bfloat162*)(pH0l + (size_t)(T_SEQ - 1) * BH),
        (const __nv_bfloat162*)(pH1h + (size_t)(T_SEQ - 1) * BH),
        (const __nv_bfloat162*)(pH1l + (size_t)(T_SEQ - 1) * BH),
        (float2*)(out + (size_t)MB_ * VOCAB));
}

// round 12
// speedup vs baseline: 1.5810x; 1.5810x over previous
#include <cuda_runtime.h>
#include <cuda_bf16.h>
#include <cuda_fp16.h>
#include <math.h>
#include <stdint.h>

#define T_SEQ 128
#define BATCH 64
#define EMB   2048
#define HID   2048
#define VOCAB 10000
#define MB_   (T_SEQ * BATCH)   /* 8192 */
#define BH    (BATCH * HID)     /* 131072 */

/* ------------------------------------------------------------------ */
/* Scratch (device globals only)                                       */
/* ------------------------------------------------------------------ */
__device__ float g_X0[(size_t)MB_ * HID];
__device__ float g_X1[(size_t)MB_ * HID];
__device__ float g_part[8][BH];
__device__ int   g_cnt[32];
__device__ int   g_is64;

__device__ __nv_bfloat16 g_emb_hi [(size_t)VOCAB * EMB];
__device__ __nv_bfloat16 g_emb_lo [(size_t)VOCAB * EMB];
__device__ __nv_bfloat16 g_w0x_hi [(size_t)HID * HID];
__device__ __nv_bfloat16 g_w0x_lo [(size_t)HID * HID];
__device__ __nv_bfloat16 g_w0h_hi [(size_t)HID * HID];
__device__ __nv_bfloat16 g_w0h_lo [(size_t)HID * HID];
__device__ __nv_bfloat16 g_w1x_hi [(size_t)HID * HID];
__device__ __nv_bfloat16 g_w1x_lo [(size_t)HID * HID];
__device__ __nv_bfloat16 g_w1h_hi [(size_t)HID * HID];
__device__ __nv_bfloat16 g_w1h_lo [(size_t)HID * HID];
__device__ __half        g_woutf  [(size_t)VOCAB * HID];   /* fp16 hi only */
__device__ __nv_bfloat16 g_H0_hi  [(size_t)MB_ * HID];
__device__ __nv_bfloat16 g_H0_lo  [(size_t)MB_ * HID];
__device__ __nv_bfloat16 g_H1_hi  [(size_t)MB_ * HID];
__device__ __nv_bfloat16 g_H1_lo  [(size_t)MB_ * HID];
__device__ __half        g_H1f_hi [(size_t)MB_ * HID];     /* fp16 mirror  */
__device__ __half        g_H1f_lo [(size_t)MB_ * HID];
__device__ __nv_bfloat16 g_hin_hi [2 * BH];
__device__ __nv_bfloat16 g_hin_lo [2 * BH];

/* ------------------------------------------------------------------ */
__device__ __forceinline__ uint32_t s2u(const void* p) {
    uint32_t a;
    asm("{ .reg .u64 t; cvta.to.shared.u64 t, %1; cvt.u32.u64 %0, t; }"
        : "=r"(a) : "l"(p));
    return a;
}
__device__ __forceinline__ void ldm_x4(uint32_t& r0, uint32_t& r1,
                                       uint32_t& r2, uint32_t& r3, uint32_t a) {
    asm volatile("ldmatrix.sync.aligned.m8n8.x4.shared.b16 {%0,%1,%2,%3}, [%4];"
                 : "=r"(r0), "=r"(r1), "=r"(r2), "=r"(r3) : "r"(a));
}
__device__ __forceinline__ void mma_bf16(float* c, const uint32_t* a,
                                         const uint32_t* b) {
    asm volatile(
        "mma.sync.aligned.m16n8k16.row.col.f32.bf16.bf16.f32 "
        "{%0,%1,%2,%3}, {%4,%5,%6,%7}, {%8,%9}, {%0,%1,%2,%3};"
        : "+f"(c[0]), "+f"(c[1]), "+f"(c[2]), "+f"(c[3])
        : "r"(a[0]), "r"(a[1]), "r"(a[2]), "r"(a[3]), "r"(b[0]), "r"(b[1]));
}
__device__ __forceinline__ void mma_f16(float* c, const uint32_t* a,
                                        const uint32_t* b) {
    asm volatile(
        "mma.sync.aligned.m16n8k16.row.col.f32.f16.f16.f32 "
        "{%0,%1,%2,%3}, {%4,%5,%6,%7}, {%8,%9}, {%0,%1,%2,%3};"
        : "+f"(c[0]), "+f"(c[1]), "+f"(c[2]), "+f"(c[3])
        : "r"(a[0]), "r"(a[1]), "r"(a[2]), "r"(a[3]), "r"(b[0]), "r"(b[1]));
}
__device__ __forceinline__ void cpa16(uint32_t dst, const void* src, int srcsz) {
    asm volatile("cp.async.cg.shared.global [%0], [%1], 16, %2;"
                 :: "r"(dst), "l"(src), "r"(srcsz) : "memory");
}
__device__ __forceinline__ void cpa_commit() {
    asm volatile("cp.async.commit_group;" ::: "memory");
}

/* ------------------------------------------------------------------ */
__global__ void detect_idx_kernel(const unsigned int* __restrict__ p) {
    if (threadIdx.x == 0) {
        unsigned int o = 0;
#pragma unroll
        for (int i = 0; i < 16; i++) o |= p[2 * i + 1];
        g_is64 = (o == 0u) ? 1 : 0;
    }
}

/* ------------------------------------------------------------------ */
/* fp32 -> bf16 hi/lo split                                            */
/* ------------------------------------------------------------------ */
__global__ void conv_split(const float4* __restrict__ src, long n4,
                           int c4s, int ld4s,
                           __nv_bfloat162* __restrict__ hi,
                           __nv_bfloat162* __restrict__ lo)
{
    long i = (long)blockIdx.x * 256 + threadIdx.x;
    if (i >= n4) return;
    long r = i >> c4s;
    long c = i & ((1L << c4s) - 1);
    float4 v = src[(r << ld4s) + c];
    __nv_bfloat16 hx = __float2bfloat16(v.x), hy = __float2bfloat16(v.y);
    __nv_bfloat16 hz = __float2bfloat16(v.z), hw = __float2bfloat16(v.w);
    __nv_bfloat162 h0; h0.x = hx; h0.y = hy;
    __nv_bfloat162 h1; h1.x = hz; h1.y = hw;
    hi[2 * i] = h0; hi[2 * i + 1] = h1;
    __nv_bfloat162 l0, l1;
    l0.x = __float2bfloat16(v.x - __bfloat162float(hx));
    l0.y = __float2bfloat16(v.y - __bfloat162float(hy));
    l1.x = __float2bfloat16(v.z - __bfloat162float(hz));
    l1.y = __float2bfloat16(v.w - __bfloat162float(hw));
    lo[2 * i] = l0; lo[2 * i + 1] = l1;
}

/* fp32 -> fp16 (hi only, for Wout) */
__global__ void conv_f16hi(const float4* __restrict__ src, long n4,
                           __half2* __restrict__ hi)
{
    long i = (long)blockIdx.x * 256 + threadIdx.x;
    if (i >= n4) return;
    float4 v = src[i];
    __half2 h0; h0.x = __float2half(v.x); h0.y = __float2half(v.y);
    __half2 h1; h1.x = __float2half(v.z); h1.y = __float2half(v.w);
    hi[2 * i] = h0; hi[2 * i + 1] = h1;
}

/* ------------------------------------------------------------------ */
/* Big mma.sync GEMM (R9 geometry: 256 thr, 8 warps 4m x 2n,           */
/* 4-stage cp.async). Templated: FP16 selects mma dtype; PASSES=3      */
/* does hi*hi + hi*lo(B) + lo(A)*hi, PASSES=2 drops the B-lo pass      */
/* (Blo never loaded).  C[M,N] = A[M,K=2048]*B[N,K]^T + bias           */
/* ------------------------------------------------------------------ */
#define ROWB   80
#define R_AHI  0
#define R_ALO  10240
#define R_BHI  20480
#define R_BLO  30720
#define STAGEB 40960
#define NSTG   4
#define GEMM_SMEM (NSTG * STAGEB)   /* 160 KB */

template<int FP16, int PASSES>
__global__ __launch_bounds__(256, 1) void gemm_mma(
    const uint16_t* __restrict__ Ahi, const uint16_t* __restrict__ Alo,
    const void* __restrict__ aidx,
    const uint16_t* __restrict__ Bhi, const uint16_t* __restrict__ Blo,
    int nrowsB, const float* __restrict__ bias,
    float* __restrict__ C, int ldc, int ncols)
{
    extern __shared__ char smem[];
    const uint32_t smbase = s2u(smem);

    const int tid  = threadIdx.x;
    const int lane = tid & 31;
    const int wid  = tid >> 5;
    const int wm   = wid & 3;
    const int wn   = wid >> 2;
    const int bm   = blockIdx.y * 128;
    const int bn   = blockIdx.x * 128;

    const int lrow  = tid >> 1;
    const int cpair = (tid & 1) * 2;
    const uint32_t dstOff = (uint32_t)(lrow * ROWB + cpair * 16);

    size_t aoff;
    {
        const int m = bm + lrow;
        size_t row;
        if (aidx) {
            if (g_is64) row = (size_t)((const long long*)aidx)[m];
            else        row = (size_t)((const int*)aidx)[m];
        } else row = (size_t)m;
        aoff = row * 2048 + (size_t)cpair * 8;
    }
    const int  nrow = bn + lrow;
    const int  bsz  = (nrow < nrowsB) ? 16 : 0;
    const size_t boff = (size_t)((nrow < nrowsB) ? nrow : 0) * 2048
                      + (size_t)cpair * 8;

    const int rlane  = lane & 15;
    const int khalf2 = (lane >> 4) * 16;
    uint32_t rowA[2], rowB[4];
#pragma unroll
    for (int mt = 0; mt < 2; mt++)
        rowA[mt] = (uint32_t)((wm * 32 + mt * 16 + rlane) * ROWB);
#pragma unroll
    for (int nt = 0; nt < 4; nt++)
        rowB[nt] = (uint32_t)((wn * 64 + nt * 16 + rlane) * ROWB);

    float acc[2][8][4];
#pragma unroll
    for (int mt = 0; mt < 2; mt++)
#pragma unroll
        for (int j = 0; j < 8; j++)
#pragma unroll
            for (int q = 0; q < 4; q++) acc[mt][j][q] = 0.f;

    const int NIT = 2048 / 32;   /* 64 */

    auto issue = [&](int it) {
        const uint32_t sb = smbase + (uint32_t)(it & (NSTG - 1)) * STAGEB;
        const size_t kb = (size_t)it * 32;
        cpa16(sb + R_AHI + dstOff,      Ahi + aoff + kb,     16);
        cpa16(sb + R_AHI + dstOff + 16, Ahi + aoff + kb + 8, 16);
        cpa16(sb + R_ALO + dstOff,      Alo + aoff + kb,     16);
        cpa16(sb + R_ALO + dstOff + 16, Alo + aoff + kb + 8, 16);
        cpa16(sb + R_BHI + dstOff,      Bhi + boff + kb,     bsz);
        cpa16(sb + R_BHI + dstOff + 16, Bhi + boff + kb + 8, bsz);
        if (PASSES == 3) {
            cpa16(sb + R_BLO + dstOff,      Blo + boff + kb,     bsz);
            cpa16(sb + R_BLO + dstOff + 16, Blo + boff + kb + 8, bsz);
        }
        cpa_commit();
    };

    issue(0); issue(1); issue(2);

    for (int it = 0; it < NIT; it++) {
        asm volatile("cp.async.wait_group 2;" ::: "memory");
        __syncthreads();
        if (it + NSTG - 1 < NIT) issue(it + NSTG - 1);
        else                     cpa_commit();

        const uint32_t sb = smbase + (uint32_t)(it & (NSTG - 1)) * STAGEB;
#pragma unroll
        for (int kk = 0; kk < 2; kk++) {
            const uint32_t kbyt = (uint32_t)(kk * 32 + khalf2);
            uint32_t ah[2][4], al[2][4];
#pragma unroll
            for (int mt = 0; mt < 2; mt++) {
                ldm_x4(ah[mt][0], ah[mt][1], ah[mt][2], ah[mt][3],
                       sb + R_AHI + rowA[mt] + kbyt);
                ldm_x4(al[mt][0], al[mt][1], al[mt][2], al[mt][3],
                       sb + R_ALO + rowA[mt] + kbyt);
            }
            uint32_t bh[8][2], bl[8][2];
#pragma unroll
            for (int nt = 0; nt < 4; nt++) {
                uint32_t t0, t1, t2, t3;
                ldm_x4(t0, t1, t2, t3, sb + R_BHI + rowB[nt] + kbyt);
                bh[2*nt][0] = t0; bh[2*nt][1] = t2;
                bh[2*nt+1][0] = t1; bh[2*nt+1][1] = t3;
                if (PASSES == 3) {
                    ldm_x4(t0, t1, t2, t3, sb + R_BLO + rowB[nt] + kbyt);
                    bl[2*nt][0] = t0; bl[2*nt][1] = t2;
                    bl[2*nt+1][0] = t1; bl[2*nt+1][1] = t3;
                }
            }
#pragma unroll
            for (int mt = 0; mt < 2; mt++)
#pragma unroll
                for (int j = 0; j < 8; j++) {
                    if (FP16) {
                        mma_f16(acc[mt][j], ah[mt], bh[j]);
                        mma_f16(acc[mt][j], al[mt], bh[j]);
                        if (PASSES == 3) mma_f16(acc[mt][j], ah[mt], bl[j]);
                    } else {
                        mma_bf16(acc[mt][j], ah[mt], bh[j]);
                        mma_bf16(acc[mt][j], al[mt], bh[j]);
                        if (PASSES == 3) mma_bf16(acc[mt][j], ah[mt], bl[j]);
                    }
                }
        }
    }

    const int gid = lane >> 2;
    const int tig = lane & 3;
#pragma unroll
    for (int mt = 0; mt < 2; mt++) {
#pragma unroll
        for (int j = 0; j < 8; j++) {
            const int col = bn + wn * 64 + j * 8 + tig * 2;
            if (col < ncols) {
                const float bx = bias[col], by = bias[col + 1];
                const size_t r0 = (size_t)(bm + wm * 32 + mt * 16 + gid);
                const size_t r1 = r0 + 8;
                float2 v0 = make_float2(acc[mt][j][0] + bx, acc[mt][j][1] + by);
                float2 v1 = make_float2(acc[mt][j][2] + bx, acc[mt][j][3] + by);
                *(float2*)(C + r0 * (size_t)ldc + col) = v0;
                *(float2*)(C + r1 * (size_t)ldc + col) = v1;
            }
        }
    }
}

/* ------------------------------------------------------------------ */
/* Recurrent step on mma.sync bf16 3-pass, 3-stage pipeline.           */
/* Finalize optionally also emits an fp16 hi/lo mirror (for logits).   */
/* ------------------------------------------------------------------ */
#define SROWB  144
#define R2_AH  0
#define R2_AL  9216
#define R2_BH  18432
#define R2_BL  27648
#define STAGE2 36864
#define STEP_SMEM (3 * STAGE2)   /* 108 KB */

__global__ __launch_bounds__(256, 1) void rnn_step_mma(
    const __nv_bfloat16* __restrict__ Ahi, const __nv_bfloat16* __restrict__ Alo,
    const __nv_bfloat16* __restrict__ Whi, const __nv_bfloat16* __restrict__ Wlo,
    const float* __restrict__ Xadd, float* __restrict__ part,
    __nv_bfloat162* __restrict__ outHi, __nv_bfloat162* __restrict__ outLo,
    __half2* __restrict__ outHi16, __half2* __restrict__ outLo16)
{
    extern __shared__ char smem[];
    __shared__ int s_last;
    const uint32_t smbase = s2u(smem);

    const int tid  = threadIdx.x;
    const int lane = tid & 31;
    const int wid  = tid >> 5;
    const int wm   = wid & 3;
    const int wn   = wid >> 2;
    const int strip  = blockIdx.x;
    const int kslice = blockIdx.y;
    const int kbase0 = kslice * 256;

    const int lrow = tid >> 2;
    const int c0   = (tid & 3) * 2;
    const uint32_t dOff = (uint32_t)(lrow * SROWB + c0 * 16);
    const size_t aO = (size_t)lrow * 2048 + (size_t)c0 * 8;
    const size_t bO = (size_t)(strip * 64 + lrow) * 2048 + (size_t)c0 * 8;

    auto issue = [&](int it) {
        const uint32_t sb = smbase + (uint32_t)(it % 3) * STAGE2;
        const size_t kb = (size_t)(kbase0 + it * 64);
        cpa16(sb + R2_AH + dOff,      Ahi + aO + kb,     16);
        cpa16(sb + R2_AH + dOff + 16, Ahi + aO + kb + 8, 16);
        cpa16(sb + R2_AL + dOff,      Alo + aO + kb,     16);
        cpa16(sb + R2_AL + dOff + 16, Alo + aO + kb + 8, 16);
        cpa16(sb + R2_BH + dOff,      Whi + bO + kb,     16);
        cpa16(sb + R2_BH + dOff + 16, Whi + bO + kb + 8, 16);
        cpa16(sb + R2_BL + dOff,      Wlo + bO + kb,     16);
        cpa16(sb + R2_BL + dOff + 16, Wlo + bO + kb + 8, 16);
        cpa_commit();
    };

    const int rlane = lane & 15;
    const int khalf = (lane >> 4) * 16;
    const uint32_t arow = (uint32_t)((wm * 16 + rlane) * SROWB);
    uint32_t brow[2];
    brow[0] = (uint32_t)((wn * 32 + rlane) * SROWB);
    brow[1] = (uint32_t)((wn * 32 + 16 + rlane) * SROWB);

    float acc[4][4];
#pragma unroll
    for (int j = 0; j < 4; j++)
#pragma unroll
        for (int q = 0; q < 4; q++) acc[j][q] = 0.f;

    issue(0); issue(1);

    for (int it = 0; it < 4; it++) {
        asm volatile("cp.async.wait_group 1;" ::: "memory");
        __syncthreads();
        if (it + 2 < 4) issue(it + 2);
        else            cpa_commit();

        const uint32_t sb = smbase + (uint32_t)(it % 3) * STAGE2;
#pragma unroll
        for (int kk = 0; kk < 4; kk++) {
            const uint32_t kbyt = (uint32_t)(kk * 32 + khalf);
            uint32_t ah[4], al[4];
            ldm_x4(ah[0], ah[1], ah[2], ah[3], sb + R2_AH + arow + kbyt);
            ldm_x4(al[0], al[1], al[2], al[3], sb + R2_AL + arow + kbyt);
            uint32_t bh[4][2], bl[4][2];
#pragma unroll
            for (int nt = 0; nt < 2; nt++) {
                uint32_t t0, t1, t2, t3;
                ldm_x4(t0, t1, t2, t3, sb + R2_BH + brow[nt] + kbyt);
                bh[2*nt][0] = t0; bh[2*nt][1] = t2;
                bh[2*nt+1][0] = t1; bh[2*nt+1][1] = t3;
                ldm_x4(t0, t1, t2, t3, sb + R2_BL + brow[nt] + kbyt);
                bl[2*nt][0] = t0; bl[2*nt][1] = t2;
                bl[2*nt+1][0] = t1; bl[2*nt+1][1] = t3;
            }
#pragma unroll
            for (int j = 0; j < 4; j++) {
                mma_bf16(acc[j], ah, bh[j]);
                mma_bf16(acc[j], ah, bl[j]);
                mma_bf16(acc[j], al, bh[j]);
            }
        }
    }

    float* dst = part + (size_t)kslice * BH;
    const int r0 = wm * 16 + (lane >> 2);
#pragma unroll
    for (int j = 0; j < 4; j++) {
        const int col = strip * 64 + wn * 32 + j * 8 + (lane & 3) * 2;
        *(float2*)(dst + (size_t)r0 * 2048 + col) =
            make_float2(acc[j][0], acc[j][1]);
        *(float2*)(dst + (size_t)(r0 + 8) * 2048 + col) =
            make_float2(acc[j][2], acc[j][3]);
    }

    __threadfence();
    if (tid == 0) {
        int old = atomicAdd(&g_cnt[strip], 1);
        s_last = (old == 7) ? 1 : 0;
    }
    __syncthreads();
    if (!s_last) return;
    __threadfence();

    const float4* p4 = (const float4*)part;
    const float4* x4 = (const float4*)Xadd;
    for (int u = tid; u < 1024; u += 256) {
        const int m  = u >> 4;
        const int c4 = u & 15;
        const size_t off = (size_t)m * 512 + (size_t)strip * 16 + c4;
        float4 sv = p4[off];
#pragma unroll
        for (int kg = 1; kg < 8; kg++) {
            float4 p = p4[(size_t)kg * (BH / 4) + off];
            sv.x += p.x; sv.y += p.y; sv.z += p.z; sv.w += p.w;
        }
        float4 xv = x4[off];
        sv.x = tanhf(sv.x + xv.x); sv.y = tanhf(sv.y + xv.y);
        sv.z = tanhf(sv.z + xv.z); sv.w = tanhf(sv.w + xv.w);

        __nv_bfloat16 hx = __float2bfloat16(sv.x), hy = __float2bfloat16(sv.y);
        __nv_bfloat16 hz = __float2bfloat16(sv.z), hw = __float2bfloat16(sv.w);
        __nv_bfloat162 a; a.x = hx; a.y = hy;
        __nv_bfloat162 b; b.x = hz; b.y = hw;
        outHi[2 * off] = a; outHi[2 * off + 1] = b;
        __nv_bfloat162 la, lb;
        la.x = __float2bfloat16(sv.x - __bfloat162float(hx));
        la.y = __float2bfloat16(sv.y - __bfloat162float(hy));
        lb.x = __float2bfloat16(sv.z - __bfloat162float(hz));
        lb.y = __float2bfloat16(sv.w - __bfloat162float(hw));
        outLo[2 * off] = la; outLo[2 * off + 1] = lb;

        if (outHi16) {
            __half fx = __float2half(sv.x), fy = __float2half(sv.y);
            __half fz = __float2half(sv.z), fw = __float2half(sv.w);
            __half2 fa; fa.x = fx; fa.y = fy;
            __half2 fb; fb.x = fz; fb.y = fw;
            outHi16[2 * off] = fa; outHi16[2 * off + 1] = fb;
            __half2 ga, gb;
            ga.x = __float2half(sv.x - __half2float(fx));
            ga.y = __float2half(sv.y - __half2float(fy));
            gb.x = __float2half(sv.z - __half2float(fz));
            gb.y = __float2half(sv.w - __half2float(fw));
            outLo16[2 * off] = ga; outLo16[2 * off + 1] = gb;
        }
    }
    __threadfence();
    __syncthreads();
    if (tid == 0) g_cnt[strip] = 0;
}

/* ------------------------------------------------------------------ */
__global__ void copy_final_hl(
    const __nv_bfloat162* __restrict__ h0h, const __nv_bfloat162* __restrict__ h0l,
    const __nv_bfloat162* __restrict__ h1h, const __nv_bfloat162* __restrict__ h1l,
    float2* __restrict__ out)
{
    const int i = blockIdx.x * 256 + threadIdx.x;
    if (i >= BH) return;
    const __nv_bfloat162 h = (i < BH / 2) ? h0h[i] : h1h[i - BH / 2];
    const __nv_bfloat162 l = (i < BH / 2) ? h0l[i] : h1l[i - BH / 2];
    float2 v;
    v.x = __bfloat162float(h.x) + __bfloat162float(l.x);
    v.y = __bfloat162float(h.y) + __bfloat162float(l.y);
    out[i] = v;
}

/* ------------------------------------------------------------------ */
extern "C" void kernel_launch(void* const* d_in, const int* in_sizes, int n_in,
                              void* d_out, int out_size)
{
    (void)in_sizes; (void)n_in; (void)out_size;

    const void*  inputs = d_in[0];
    const float* hidden = (const float*)d_in[1];
    const float* emb    = (const float*)d_in[2];
    const float* W0     = (const float*)d_in[3];
    const float* b0     = (const float*)d_in[4];
    const float* W1     = (const float*)d_in[5];
    const float* b1     = (const float*)d_in[6];
    const float* Wout   = (const float*)d_in[7];
    const float* bout   = (const float*)d_in[8];
    float* out = (float*)d_out;

    float *pX0, *pX1, *pPart;
    __nv_bfloat16 *pEh, *pEl, *pW0xh, *pW0xl, *pW0hh, *pW0hl;
    __nv_bfloat16 *pW1xh, *pW1xl, *pW1hh, *pW1hl;
    __nv_bfloat16 *pH0h, *pH0l, *pH1h, *pH1l, *pHIh, *pHIl;
    __half *pWof, *pH1fh, *pH1fl;
    cudaGetSymbolAddress((void**)&pX0,   g_X0);
    cudaGetSymbolAddress((void**)&pX1,   g_X1);
    cudaGetSymbolAddress((void**)&pPart, g_part);
    cudaGetSymbolAddress((void**)&pEh,   g_emb_hi);
    cudaGetSymbolAddress((void**)&pEl,   g_emb_lo);
    cudaGetSymbolAddress((void**)&pW0xh, g_w0x_hi);
    cudaGetSymbolAddress((void**)&pW0xl, g_w0x_lo);
    cudaGetSymbolAddress((void**)&pW0hh, g_w0h_hi);
    cudaGetSymbolAddress((void**)&pW0hl, g_w0h_lo);
    cudaGetSymbolAddress((void**)&pW1xh, g_w1x_hi);
    cudaGetSymbolAddress((void**)&pW1xl, g_w1x_lo);
    cudaGetSymbolAddress((void**)&pW1hh, g_w1h_hi);
    cudaGetSymbolAddress((void**)&pW1hl, g_w1h_lo);
    cudaGetSymbolAddress((void**)&pWof,  g_woutf);
    cudaGetSymbolAddress((void**)&pH0h,  g_H0_hi);
    cudaGetSymbolAddress((void**)&pH0l,  g_H0_lo);
    cudaGetSymbolAddress((void**)&pH1h,  g_H1_hi);
    cudaGetSymbolAddress((void**)&pH1l,  g_H1_lo);
    cudaGetSymbolAddress((void**)&pH1fh, g_H1f_hi);
    cudaGetSymbolAddress((void**)&pH1fl, g_H1f_lo);
    cudaGetSymbolAddress((void**)&pHIh,  g_hin_hi);
    cudaGetSymbolAddress((void**)&pHIl,  g_hin_lo);

    static int smem_set = 0;
    if (!smem_set) {
        cudaFuncSetAttribute(gemm_mma<0,3>,
                             cudaFuncAttributeMaxDynamicSharedMemorySize, GEMM_SMEM);
        cudaFuncSetAttribute(gemm_mma<1,2>,
                             cudaFuncAttributeMaxDynamicSharedMemorySize, GEMM_SMEM);
        cudaFuncSetAttribute(rnn_step_mma,
                             cudaFuncAttributeMaxDynamicSharedMemorySize, STEP_SMEM);
        smem_set = 1;
    }

    detect_idx_kernel<<<1, 32>>>((const unsigned int*)inputs);

    /* hi/lo conversions */
    {
        long n4;
        n4 = (long)VOCAB * (EMB / 4);
        conv_split<<<(unsigned)((n4 + 255) / 256), 256>>>(
            (const float4*)emb, n4, 9, 9, (__nv_bfloat162*)pEh, (__nv_bfloat162*)pEl);
        n4 = (long)VOCAB * (HID / 4);
        conv_f16hi<<<(unsigned)((n4 + 255) / 256), 256>>>(
            (const float4*)Wout, n4, (__half2*)pWof);
        n4 = (long)HID * (HID / 4);
        conv_split<<<(unsigned)((n4 + 255) / 256), 256>>>(
            (const float4*)W0, n4, 9, 10,
            (__nv_bfloat162*)pW0xh, (__nv_bfloat162*)pW0xl);
        conv_split<<<(unsigned)((n4 + 255) / 256), 256>>>(
            (const float4*)(W0 + 2048), n4, 9, 10,
            (__nv_bfloat162*)pW0hh, (__nv_bfloat162*)pW0hl);
        conv_split<<<(unsigned)((n4 + 255) / 256), 256>>>(
            (const float4*)W1, n4, 9, 10,
            (__nv_bfloat162*)pW1xh, (__nv_bfloat162*)pW1xl);
        conv_split<<<(unsigned)((n4 + 255) / 256), 256>>>(
            (const float4*)(W1 + 2048), n4, 9, 10,
            (__nv_bfloat162*)pW1hh, (__nv_bfloat162*)pW1hl);
        n4 = (long)(2 * BH) / 4;
        conv_split<<<(unsigned)((n4 + 255) / 256), 256>>>(
            (const float4*)hidden, n4, 9, 9,
            (__nv_bfloat162*)pHIh, (__nv_bfloat162*)pHIl);
    }

    /* X0 = emb[inputs] @ W0x^T + b0   (bf16, 3-pass) */
    {
        dim3 g(HID / 128, MB_ / 128);
        gemm_mma<0,3><<<g, 256, GEMM_SMEM>>>(
            (const uint16_t*)pEh, (const uint16_t*)pEl, inputs,
            (const uint16_t*)pW0xh, (const uint16_t*)pW0xl,
            HID, b0, pX0, HID, HID);
    }

    const dim3 gs(32, 8);

    /* layer-0 recurrence */
    for (int t = 0; t < T_SEQ; t++) {
        const __nv_bfloat16* ah = t ? (pH0h + (size_t)(t - 1) * BH) : pHIh;
        const __nv_bfloat16* al = t ? (pH0l + (size_t)(t - 1) * BH) : pHIl;
        rnn_step_mma<<<gs, 256, STEP_SMEM>>>(
            ah, al, pW0hh, pW0hl, pX0 + (size_t)t * BH, pPart,
            (__nv_bfloat162*)(pH0h + (size_t)t * BH),
            (__nv_bfloat162*)(pH0l + (size_t)t * BH),
            (__half2*)0, (__half2*)0);
    }

    /* X1 = H0 @ W1x^T + b1   (bf16, 3-pass) */
    {
        dim3 g(HID / 128, MB_ / 128);
        gemm_mma<0,3><<<g, 256, GEMM_SMEM>>>(
            (const uint16_t*)pH0h, (const uint16_t*)pH0l, (const void*)0,
            (const uint16_t*)pW1xh, (const uint16_t*)pW1xl,
            HID, b1, pX1, HID, HID);
    }

    /* layer-1 recurrence (emits fp16 mirror of H1 for logits) */
    for (int t = 0; t < T_SEQ; t++) {
        const __nv_bfloat16* ah = t ? (pH1h + (size_t)(t - 1) * BH) : (pHIh + BH);
        const __nv_bfloat16* al = t ? (pH1l + (size_t)(t - 1) * BH) : (pHIl + BH);
        rnn_step_mma<<<gs, 256, STEP_SMEM>>>(
            ah, al, pW1hh, pW1hl, pX1 + (size_t)t * BH, pPart,
            (__nv_bfloat162*)(pH1h + (size_t)t * BH),
            (__nv_bfloat162*)(pH1l + (size_t)t * BH),
            (__half2*)(pH1fh + (size_t)t * BH),
            (__half2*)(pH1fl + (size_t)t * BH));
    }

    /* logits = H1 @ Wout^T + bout   (fp16, 2-pass: Hh*Wh + Hl*Wh) */
    {
        dim3 g((VOCAB + 127) / 128, MB_ / 128);
        gemm_mma<1,2><<<g, 256, GEMM_SMEM>>>(
            (const uint16_t*)pH1fh, (const uint16_t*)pH1fl, (const void*)0,
            (const uint16_t*)pWof, (const uint16_t*)0,
            VOCAB, bout, out, VOCAB, VOCAB);
    }

    copy_final_hl<<<(BH + 255) / 256, 256>>>(
        (const __nv_bfloat162*)(pH0h + (size_t)(T_SEQ - 1) * BH),
        (const __nv_bfloat162*)(pH0l + (size_t)(T_SEQ - 1) * BH),
        (const __nv_bfloat162*)(pH1h + (size_t)(T_SEQ - 1) * BH),
        (const __nv_bfloat162*)(pH1l + (size_t)(T_SEQ - 1) * BH),
        (float2*)(out + (size_t)MB_ * VOCAB));
}

// round 13
// speedup vs baseline: 1.8090x; 1.1441x over previous
#include <cuda_runtime.h>
#include <cuda_bf16.h>
#include <cuda_fp16.h>
#include <math.h>
#include <stdint.h>

#define T_SEQ 128
#define BATCH 64
#define EMB   2048
#define HID   2048
#define VOCAB 10000
#define MB_   (T_SEQ * BATCH)   /* 8192 */
#define BH    (BATCH * HID)     /* 131072 */

/* ------------------------------------------------------------------ */
/* Scratch (device globals only)                                       */
/* ------------------------------------------------------------------ */
__device__ float g_X0[(size_t)MB_ * HID];
__device__ float g_X1[(size_t)MB_ * HID];
__device__ float g_part[8][BH];
__device__ int   g_cnt[32];
__device__ int   g_is64;

__device__ __nv_bfloat16 g_emb_hi [(size_t)VOCAB * EMB];
__device__ __nv_bfloat16 g_emb_lo [(size_t)VOCAB * EMB];
__device__ __nv_bfloat16 g_w0x_hi [(size_t)HID * HID];
__device__ __nv_bfloat16 g_w0x_lo [(size_t)HID * HID];
__device__ __nv_bfloat16 g_w0h_hi [(size_t)HID * HID];
__device__ __nv_bfloat16 g_w0h_lo [(size_t)HID * HID];
__device__ __nv_bfloat16 g_w1x_hi [(size_t)HID * HID];
__device__ __nv_bfloat16 g_w1x_lo [(size_t)HID * HID];
__device__ __nv_bfloat16 g_w1h_hi [(size_t)HID * HID];
__device__ __nv_bfloat16 g_w1h_lo [(size_t)HID * HID];
__device__ __half        g_woutf  [(size_t)VOCAB * HID];   /* fp16 hi only */
__device__ __nv_bfloat16 g_H0_hi  [(size_t)MB_ * HID];
__device__ __nv_bfloat16 g_H0_lo  [(size_t)MB_ * HID];
__device__ __nv_bfloat16 g_H1_hi  [(size_t)MB_ * HID];
__device__ __nv_bfloat16 g_H1_lo  [(size_t)MB_ * HID];
__device__ __half        g_H1f_hi [(size_t)MB_ * HID];     /* fp16 mirror  */
__device__ __nv_bfloat16 g_hin_hi [2 * BH];
__device__ __nv_bfloat16 g_hin_lo [2 * BH];

/* ------------------------------------------------------------------ */
__device__ __forceinline__ uint32_t s2u(const void* p) {
    uint32_t a;
    asm("{ .reg .u64 t; cvta.to.shared.u64 t, %1; cvt.u32.u64 %0, t; }"
        : "=r"(a) : "l"(p));
    return a;
}
__device__ __forceinline__ void ldm_x4(uint32_t& r0, uint32_t& r1,
                                       uint32_t& r2, uint32_t& r3, uint32_t a) {
    asm volatile("ldmatrix.sync.aligned.m8n8.x4.shared.b16 {%0,%1,%2,%3}, [%4];"
                 : "=r"(r0), "=r"(r1), "=r"(r2), "=r"(r3) : "r"(a));
}
__device__ __forceinline__ void mma_bf16(float* c, const uint32_t* a,
                                         const uint32_t* b) {
    asm volatile(
        "mma.sync.aligned.m16n8k16.row.col.f32.bf16.bf16.f32 "
        "{%0,%1,%2,%3}, {%4,%5,%6,%7}, {%8,%9}, {%0,%1,%2,%3};"
        : "+f"(c[0]), "+f"(c[1]), "+f"(c[2]), "+f"(c[3])
        : "r"(a[0]), "r"(a[1]), "r"(a[2]), "r"(a[3]), "r"(b[0]), "r"(b[1]));
}
__device__ __forceinline__ void mma_f16(float* c, const uint32_t* a,
                                        const uint32_t* b) {
    asm volatile(
        "mma.sync.aligned.m16n8k16.row.col.f32.f16.f16.f32 "
        "{%0,%1,%2,%3}, {%4,%5,%6,%7}, {%8,%9}, {%0,%1,%2,%3};"
        : "+f"(c[0]), "+f"(c[1]), "+f"(c[2]), "+f"(c[3])
        : "r"(a[0]), "r"(a[1]), "r"(a[2]), "r"(a[3]), "r"(b[0]), "r"(b[1]));
}
__device__ __forceinline__ void cpa16(uint32_t dst, const void* src, int srcsz) {
    asm volatile("cp.async.cg.shared.global [%0], [%1], 16, %2;"
                 :: "r"(dst), "l"(src), "r"(srcsz) : "memory");
}
__device__ __forceinline__ void cpa_commit() {
    asm volatile("cp.async.commit_group;" ::: "memory");
}

/* ------------------------------------------------------------------ */
__global__ void detect_idx_kernel(const unsigned int* __restrict__ p) {
    if (threadIdx.x == 0) {
        unsigned int o = 0;
#pragma unroll
        for (int i = 0; i < 16; i++) o |= p[2 * i + 1];
        g_is64 = (o == 0u) ? 1 : 0;
    }
}

/* ------------------------------------------------------------------ */
/* fp32 -> bf16 hi/lo split                                            */
/* ------------------------------------------------------------------ */
__global__ void conv_split(const float4* __restrict__ src, long n4,
                           int c4s, int ld4s,
                           __nv_bfloat162* __restrict__ hi,
                           __nv_bfloat162* __restrict__ lo)
{
    long i = (long)blockIdx.x * 256 + threadIdx.x;
    if (i >= n4) return;
    long r = i >> c4s;
    long c = i & ((1L << c4s) - 1);
    float4 v = src[(r << ld4s) + c];
    __nv_bfloat16 hx = __float2bfloat16(v.x), hy = __float2bfloat16(v.y);
    __nv_bfloat16 hz = __float2bfloat16(v.z), hw = __float2bfloat16(v.w);
    __nv_bfloat162 h0; h0.x = hx; h0.y = hy;
    __nv_bfloat162 h1; h1.x = hz; h1.y = hw;
    hi[2 * i] = h0; hi[2 * i + 1] = h1;
    __nv_bfloat162 l0, l1;
    l0.x = __float2bfloat16(v.x - __bfloat162float(hx));
    l0.y = __float2bfloat16(v.y - __bfloat162float(hy));
    l1.x = __float2bfloat16(v.z - __bfloat162float(hz));
    l1.y = __float2bfloat16(v.w - __bfloat162float(hw));
    lo[2 * i] = l0; lo[2 * i + 1] = l1;
}

/* fp32 -> fp16 (hi only, for Wout) */
__global__ void conv_f16hi(const float4* __restrict__ src, long n4,
                           __half2* __restrict__ hi)
{
    long i = (long)blockIdx.x * 256 + threadIdx.x;
    if (i >= n4) return;
    float4 v = src[i];
    __half2 h0; h0.x = __float2half(v.x); h0.y = __float2half(v.y);
    __half2 h1; h1.x = __float2half(v.z); h1.y = __float2half(v.w);
    hi[2 * i] = h0; hi[2 * i + 1] = h1;
}

/* ------------------------------------------------------------------ */
/* Big mma.sync GEMM (R9 geometry: 256 thr, 8 warps 4m x 2n,           */
/* 4-stage cp.async). Templated: FP16 selects mma dtype.               */
/*   PASSES=3: hi*hi + hi*lo(B) + lo(A)*hi                             */
/*   PASSES=2: hi*hi + lo(A)*hi          (Blo never loaded)            */
/*   PASSES=1: hi*hi                     (Alo, Blo never loaded)       */
/* C[M,N] = A[M,K=2048]*B[N,K]^T + bias                                */
/* ------------------------------------------------------------------ */
#define ROWB   80
#define R_AHI  0
#define R_ALO  10240
#define R_BHI  20480
#define R_BLO  30720
#define STAGEB 40960
#define NSTG   4
#define GEMM_SMEM (NSTG * STAGEB)   /* 160 KB */

template<int FP16, int PASSES>
__global__ __launch_bounds__(256, 1) void gemm_mma(
    const uint16_t* __restrict__ Ahi, const uint16_t* __restrict__ Alo,
    const void* __restrict__ aidx,
    const uint16_t* __restrict__ Bhi, const uint16_t* __restrict__ Blo,
    int nrowsB, const float* __restrict__ bias,
    float* __restrict__ C, int ldc, int ncols)
{
    extern __shared__ char smem[];
    const uint32_t smbase = s2u(smem);

    const int tid  = threadIdx.x;
    const int lane = tid & 31;
    const int wid  = tid >> 5;
    const int wm   = wid & 3;
    const int wn   = wid >> 2;
    const int bm   = blockIdx.y * 128;
    const int bn   = blockIdx.x * 128;

    const int lrow  = tid >> 1;
    const int cpair = (tid & 1) * 2;
    const uint32_t dstOff = (uint32_t)(lrow * ROWB + cpair * 16);

    size_t aoff;
    {
        const int m = bm + lrow;
        size_t row;
        if (aidx) {
            if (g_is64) row = (size_t)((const long long*)aidx)[m];
            else        row = (size_t)((const int*)aidx)[m];
        } else row = (size_t)m;
        aoff = row * 2048 + (size_t)cpair * 8;
    }
    const int  nrow = bn + lrow;
    const int  bsz  = (nrow < nrowsB) ? 16 : 0;
    const size_t boff = (size_t)((nrow < nrowsB) ? nrow : 0) * 2048
                      + (size_t)cpair * 8;

    const int rlane  = lane & 15;
    const int khalf2 = (lane >> 4) * 16;
    uint32_t rowA[2], rowB[4];
#pragma unroll
    for (int mt = 0; mt < 2; mt++)
        rowA[mt] = (uint32_t)((wm * 32 + mt * 16 + rlane) * ROWB);
#pragma unroll
    for (int nt = 0; nt < 4; nt++)
        rowB[nt] = (uint32_t)((wn * 64 + nt * 16 + rlane) * ROWB);

    float acc[2][8][4];
#pragma unroll
    for (int mt = 0; mt < 2; mt++)
#pragma unroll
        for (int j = 0; j < 8; j++)
#pragma unroll
            for (int q = 0; q < 4; q++) acc[mt][j][q] = 0.f;

    const int NIT = 2048 / 32;   /* 64 */

    auto issue = [&](int it) {
        const uint32_t sb = smbase + (uint32_t)(it & (NSTG - 1)) * STAGEB;
        const size_t kb = (size_t)it * 32;
        cpa16(sb + R_AHI + dstOff,      Ahi + aoff + kb,     16);
        cpa16(sb + R_AHI + dstOff + 16, Ahi + aoff + kb + 8, 16);
        if (PASSES >= 2) {
            cpa16(sb + R_ALO + dstOff,      Alo + aoff + kb,     16);
            cpa16(sb + R_ALO + dstOff + 16, Alo + aoff + kb + 8, 16);
        }
        cpa16(sb + R_BHI + dstOff,      Bhi + boff + kb,     bsz);
        cpa16(sb + R_BHI + dstOff + 16, Bhi + boff + kb + 8, bsz);
        if (PASSES == 3) {
            cpa16(sb + R_BLO + dstOff,      Blo + boff + kb,     bsz);
            cpa16(sb + R_BLO + dstOff + 16, Blo + boff + kb + 8, bsz);
        }
        cpa_commit();
    };

    issue(0); issue(1); issue(2);

    for (int it = 0; it < NIT; it++) {
        asm volatile("cp.async.wait_group 2;" ::: "memory");
        __syncthreads();
        if (it + NSTG - 1 < NIT) issue(it + NSTG - 1);
        else                     cpa_commit();

        const uint32_t sb = smbase + (uint32_t)(it & (NSTG - 1)) * STAGEB;
#pragma unroll
        for (int kk = 0; kk < 2; kk++) {
            const uint32_t kbyt = (uint32_t)(kk * 32 + khalf2);
            uint32_t ah[2][4], al[2][4];
#pragma unroll
            for (int mt = 0; mt < 2; mt++) {
                ldm_x4(ah[mt][0], ah[mt][1], ah[mt][2], ah[mt][3],
                       sb + R_AHI + rowA[mt] + kbyt);
                if (PASSES >= 2)
                    ldm_x4(al[mt][0], al[mt][1], al[mt][2], al[mt][3],
                           sb + R_ALO + rowA[mt] + kbyt);
            }
            uint32_t bh[8][2], bl[8][2];
#pragma unroll
            for (int nt = 0; nt < 4; nt++) {
                uint32_t t0, t1, t2, t3;
                ldm_x4(t0, t1, t2, t3, sb + R_BHI + rowB[nt] + kbyt);
                bh[2*nt][0] = t0; bh[2*nt][1] = t2;
                bh[2*nt+1][0] = t1; bh[2*nt+1][1] = t3;
                if (PASSES == 3) {
                    ldm_x4(t0, t1, t2, t3, sb + R_BLO + rowB[nt] + kbyt);
                    bl[2*nt][0] = t0; bl[2*nt][1] = t2;
                    bl[2*nt+1][0] = t1; bl[2*nt+1][1] = t3;
                }
            }
#pragma unroll
            for (int mt = 0; mt < 2; mt++)
#pragma unroll
                for (int j = 0; j < 8; j++) {
                    if (FP16) {
                        mma_f16(acc[mt][j], ah[mt], bh[j]);
                        if (PASSES >= 2) mma_f16(acc[mt][j], al[mt], bh[j]);
                        if (PASSES == 3) mma_f16(acc[mt][j], ah[mt], bl[j]);
                    } else {
                        mma_bf16(acc[mt][j], ah[mt], bh[j]);
                        if (PASSES >= 2) mma_bf16(acc[mt][j], al[mt], bh[j]);
                        if (PASSES == 3) mma_bf16(acc[mt][j], ah[mt], bl[j]);
                    }
                }
        }
    }

    const int gid = lane >> 2;
    const int tig = lane & 3;
#pragma unroll
    for (int mt = 0; mt < 2; mt++) {
#pragma unroll
        for (int j = 0; j < 8; j++) {
            const int col = bn + wn * 64 + j * 8 + tig * 2;
            if (col < ncols) {
                const float bx = bias[col], by = bias[col + 1];
                const size_t r0 = (size_t)(bm + wm * 32 + mt * 16 + gid);
                const size_t r1 = r0 + 8;
                float2 v0 = make_float2(acc[mt][j][0] + bx, acc[mt][j][1] + by);
                float2 v1 = make_float2(acc[mt][j][2] + bx, acc[mt][j][3] + by);
                *(float2*)(C + r0 * (size_t)ldc + col) = v0;
                *(float2*)(C + r1 * (size_t)ldc + col) = v1;
            }
        }
    }
}

/* ------------------------------------------------------------------ */
/* Recurrent step on mma.sync bf16 3-pass, 3-stage pipeline.           */
/* Finalize optionally also emits an fp16-hi mirror (for logits).      */
/* ------------------------------------------------------------------ */
#define SROWB  144
#define R2_AH  0
#define R2_AL  9216
#define R2_BH  18432
#define R2_BL  27648
#define STAGE2 36864
#define STEP_SMEM (3 * STAGE2)   /* 108 KB */

__global__ __launch_bounds__(256, 1) void rnn_step_mma(
    const __nv_bfloat16* __restrict__ Ahi, const __nv_bfloat16* __restrict__ Alo,
    const __nv_bfloat16* __restrict__ Whi, const __nv_bfloat16* __restrict__ Wlo,
    const float* __restrict__ Xadd, float* __restrict__ part,
    __nv_bfloat162* __restrict__ outHi, __nv_bfloat162* __restrict__ outLo,
    __half2* __restrict__ outHi16)
{
    extern __shared__ char smem[];
    __shared__ int s_last;
    const uint32_t smbase = s2u(smem);

    const int tid  = threadIdx.x;
    const int lane = tid & 31;
    const int wid  = tid >> 5;
    const int wm   = wid & 3;
    const int wn   = wid >> 2;
    const int strip  = blockIdx.x;
    const int kslice = blockIdx.y;
    const int kbase0 = kslice * 256;

    const int lrow = tid >> 2;
    const int c0   = (tid & 3) * 2;
    const uint32_t dOff = (uint32_t)(lrow * SROWB + c0 * 16);
    const size_t aO = (size_t)lrow * 2048 + (size_t)c0 * 8;
    const size_t bO = (size_t)(strip * 64 + lrow) * 2048 + (size_t)c0 * 8;

    auto issue = [&](int it) {
        const uint32_t sb = smbase + (uint32_t)(it % 3) * STAGE2;
        const size_t kb = (size_t)(kbase0 + it * 64);
        cpa16(sb + R2_AH + dOff,      Ahi + aO + kb,     16);
        cpa16(sb + R2_AH + dOff + 16, Ahi + aO + kb + 8, 16);
        cpa16(sb + R2_AL + dOff,      Alo + aO + kb,     16);
        cpa16(sb + R2_AL + dOff + 16, Alo + aO + kb + 8, 16);
        cpa16(sb + R2_BH + dOff,      Whi + bO + kb,     16);
        cpa16(sb + R2_BH + dOff + 16, Whi + bO + kb + 8, 16);
        cpa16(sb + R2_BL + dOff,      Wlo + bO + kb,     16);
        cpa16(sb + R2_BL + dOff + 16, Wlo + bO + kb + 8, 16);
        cpa_commit();
    };

    const int rlane = lane & 15;
    const int khalf = (lane >> 4) * 16;
    const uint32_t arow = (uint32_t)((wm * 16 + rlane) * SROWB);
    uint32_t brow[2];
    brow[0] = (uint32_t)((wn * 32 + rlane) * SROWB);
    brow[1] = (uint32_t)((wn * 32 + 16 + rlane) * SROWB);

    float acc[4][4];
#pragma unroll
    for (int j = 0; j < 4; j++)
#pragma unroll
        for (int q = 0; q < 4; q++) acc[j][q] = 0.f;

    issue(0); issue(1);

    for (int it = 0; it < 4; it++) {
        asm volatile("cp.async.wait_group 1;" ::: "memory");
        __syncthreads();
        if (it + 2 < 4) issue(it + 2);
        else            cpa_commit();

        const uint32_t sb = smbase + (uint32_t)(it % 3) * STAGE2;
#pragma unroll
        for (int kk = 0; kk < 4; kk++) {
            const uint32_t kbyt = (uint32_t)(kk * 32 + khalf);
            uint32_t ah[4], al[4];
            ldm_x4(ah[0], ah[1], ah[2], ah[3], sb + R2_AH + arow + kbyt);
            ldm_x4(al[0], al[1], al[2], al[3], sb + R2_AL + arow + kbyt);
            uint32_t bh[4][2], bl[4][2];
#pragma unroll
            for (int nt = 0; nt < 2; nt++) {
                uint32_t t0, t1, t2, t3;
                ldm_x4(t0, t1, t2, t3, sb + R2_BH + brow[nt] + kbyt);
                bh[2*nt][0] = t0; bh[2*nt][1] = t2;
                bh[2*nt+1][0] = t1; bh[2*nt+1][1] = t3;
                ldm_x4(t0, t1, t2, t3, sb + R2_BL + brow[nt] + kbyt);
                bl[2*nt][0] = t0; bl[2*nt][1] = t2;
                bl[2*nt+1][0] = t1; bl[2*nt+1][1] = t3;
            }
#pragma unroll
            for (int j = 0; j < 4; j++) {
                mma_bf16(acc[j], ah, bh[j]);
                mma_bf16(acc[j], ah, bl[j]);
                mma_bf16(acc[j], al, bh[j]);
            }
        }
    }

    float* dst = part + (size_t)kslice * BH;
    const int r0 = wm * 16 + (lane >> 2);
#pragma unroll
    for (int j = 0; j < 4; j++) {
        const int col = strip * 64 + wn * 32 + j * 8 + (lane & 3) * 2;
        *(float2*)(dst + (size_t)r0 * 2048 + col) =
            make_float2(acc[j][0], acc[j][1]);
        *(float2*)(dst + (size_t)(r0 + 8) * 2048 + col) =
            make_float2(acc[j][2], acc[j][3]);
    }

    __threadfence();
    if (tid == 0) {
        int old = atomicAdd(&g_cnt[strip], 1);
        s_last = (old == 7) ? 1 : 0;
    }
    __syncthreads();
    if (!s_last) return;
    __threadfence();

    const float4* p4 = (const float4*)part;
    const float4* x4 = (const float4*)Xadd;
    for (int u = tid; u < 1024; u += 256) {
        const int m  = u >> 4;
        const int c4 = u & 15;
        const size_t off = (size_t)m * 512 + (size_t)strip * 16 + c4;
        float4 sv = p4[off];
#pragma unroll
        for (int kg = 1; kg < 8; kg++) {
            float4 p = p4[(size_t)kg * (BH / 4) + off];
            sv.x += p.x; sv.y += p.y; sv.z += p.z; sv.w += p.w;
        }
        float4 xv = x4[off];
        sv.x = tanhf(sv.x + xv.x); sv.y = tanhf(sv.y + xv.y);
        sv.z = tanhf(sv.z + xv.z); sv.w = tanhf(sv.w + xv.w);

        __nv_bfloat16 hx = __float2bfloat16(sv.x), hy = __float2bfloat16(sv.y);
        __nv_bfloat16 hz = __float2bfloat16(sv.z), hw = __float2bfloat16(sv.w);
        __nv_bfloat162 a; a.x = hx; a.y = hy;
        __nv_bfloat162 b; b.x = hz; b.y = hw;
        outHi[2 * off] = a; outHi[2 * off + 1] = b;
        __nv_bfloat162 la, lb;
        la.x = __float2bfloat16(sv.x - __bfloat162float(hx));
        la.y = __float2bfloat16(sv.y - __bfloat162float(hy));
        lb.x = __float2bfloat16(sv.z - __bfloat162float(hz));
        lb.y = __float2bfloat16(sv.w - __bfloat162float(hw));
        outLo[2 * off] = la; outLo[2 * off + 1] = lb;

        if (outHi16) {
            __half2 fa; fa.x = __float2half(sv.x); fa.y = __float2half(sv.y);
            __half2 fb; fb.x = __float2half(sv.z); fb.y = __float2half(sv.w);
            outHi16[2 * off] = fa; outHi16[2 * off + 1] = fb;
        }
    }
    __threadfence();
    __syncthreads();
    if (tid == 0) g_cnt[strip] = 0;
}

/* ------------------------------------------------------------------ */
__global__ void copy_final_hl(
    const __nv_bfloat162* __restrict__ h0h, const __nv_bfloat162* __restrict__ h0l,
    const __nv_bfloat162* __restrict__ h1h, const __nv_bfloat162* __restrict__ h1l,
    float2* __restrict__ out)
{
    const int i = blockIdx.x * 256 + threadIdx.x;
    if (i >= BH) return;
    const __nv_bfloat162 h = (i < BH / 2) ? h0h[i] : h1h[i - BH / 2];
    const __nv_bfloat162 l = (i < BH / 2) ? h0l[i] : h1l[i - BH / 2];
    float2 v;
    v.x = __bfloat162float(h.x) + __bfloat162float(l.x);
    v.y = __bfloat162float(h.y) + __bfloat162float(l.y);
    out[i] = v;
}

/* ------------------------------------------------------------------ */
extern "C" void kernel_launch(void* const* d_in, const int* in_sizes, int n_in,
                              void* d_out, int out_size)
{
    (void)in_sizes; (void)n_in; (void)out_size;

    const void*  inputs = d_in[0];
    const float* hidden = (const float*)d_in[1];
    const float* emb    = (const float*)d_in[2];
    const float* W0     = (const float*)d_in[3];
    const float* b0     = (const float*)d_in[4];
    const float* W1     = (const float*)d_in[5];
    const float* b1     = (const float*)d_in[6];
    const float* Wout   = (const float*)d_in[7];
    const float* bout   = (const float*)d_in[8];
    float* out = (float*)d_out;

    float *pX0, *pX1, *pPart;
    __nv_bfloat16 *pEh, *pEl, *pW0xh, *pW0xl, *pW0hh, *pW0hl;
    __nv_bfloat16 *pW1xh, *pW1xl, *pW1hh, *pW1hl;
    __nv_bfloat16 *pH0h, *pH0l, *pH1h, *pH1l, *pHIh, *pHIl;
    __half *pWof, *pH1fh;
    cudaGetSymbolAddress((void**)&pX0,   g_X0);
    cudaGetSymbolAddress((void**)&pX1,   g_X1);
    cudaGetSymbolAddress((void**)&pPart, g_part);
    cudaGetSymbolAddress((void**)&pEh,   g_emb_hi);
    cudaGetSymbolAddress((void**)&pEl,   g_emb_lo);
    cudaGetSymbolAddress((void**)&pW0xh, g_w0x_hi);
    cudaGetSymbolAddress((void**)&pW0xl, g_w0x_lo);
    cudaGetSymbolAddress((void**)&pW0hh, g_w0h_hi);
    cudaGetSymbolAddress((void**)&pW0hl, g_w0h_lo);
    cudaGetSymbolAddress((void**)&pW1xh, g_w1x_hi);
    cudaGetSymbolAddress((void**)&pW1xl, g_w1x_lo);
    cudaGetSymbolAddress((void**)&pW1hh, g_w1h_hi);
    cudaGetSymbolAddress((void**)&pW1hl, g_w1h_lo);
    cudaGetSymbolAddress((void**)&pWof,  g_woutf);
    cudaGetSymbolAddress((void**)&pH0h,  g_H0_hi);
    cudaGetSymbolAddress((void**)&pH0l,  g_H0_lo);
    cudaGetSymbolAddress((void**)&pH1h,  g_H1_hi);
    cudaGetSymbolAddress((void**)&pH1l,  g_H1_lo);
    cudaGetSymbolAddress((void**)&pH1fh, g_H1f_hi);
    cudaGetSymbolAddress((void**)&pHIh,  g_hin_hi);
    cudaGetSymbolAddress((void**)&pHIl,  g_hin_lo);

    static int smem_set = 0;
    if (!smem_set) {
        cudaFuncSetAttribute(gemm_mma<0,3>,
                             cudaFuncAttributeMaxDynamicSharedMemorySize, GEMM_SMEM);
        cudaFuncSetAttribute(gemm_mma<1,1>,
                             cudaFuncAttributeMaxDynamicSharedMemorySize, GEMM_SMEM);
        cudaFuncSetAttribute(rnn_step_mma,
                             cudaFuncAttributeMaxDynamicSharedMemorySize, STEP_SMEM);
        smem_set = 1;
    }

    detect_idx_kernel<<<1, 32>>>((const unsigned int*)inputs);

    /* hi/lo conversions */
    {
        long n4;
        n4 = (long)VOCAB * (EMB / 4);
        conv_split<<<(unsigned)((n4 + 255) / 256), 256>>>(
            (const float4*)emb, n4, 9, 9, (__nv_bfloat162*)pEh, (__nv_bfloat162*)pEl);
        n4 = (long)VOCAB * (HID / 4);
        conv_f16hi<<<(unsigned)((n4 + 255) / 256), 256>>>(
            (const float4*)Wout, n4, (__half2*)pWof);
        n4 = (long)HID * (HID / 4);
        conv_split<<<(unsigned)((n4 + 255) / 256), 256>>>(
            (const float4*)W0, n4, 9, 10,
            (__nv_bfloat162*)pW0xh, (__nv_bfloat162*)pW0xl);
        conv_split<<<(unsigned)((n4 + 255) / 256), 256>>>(
            (const float4*)(W0 + 2048), n4, 9, 10,
            (__nv_bfloat162*)pW0hh, (__nv_bfloat162*)pW0hl);
        conv_split<<<(unsigned)((n4 + 255) / 256), 256>>>(
            (const float4*)W1, n4, 9, 10,
            (__nv_bfloat162*)pW1xh, (__nv_bfloat162*)pW1xl);
        conv_split<<<(unsigned)((n4 + 255) / 256), 256>>>(
            (const float4*)(W1 + 2048), n4, 9, 10,
            (__nv_bfloat162*)pW1hh, (__nv_bfloat162*)pW1hl);
        n4 = (long)(2 * BH) / 4;
        conv_split<<<(unsigned)((n4 + 255) / 256), 256>>>(
            (const float4*)hidden, n4, 9, 9,
            (__nv_bfloat162*)pHIh, (__nv_bfloat162*)pHIl);
    }

    /* X0 = emb[inputs] @ W0x^T + b0   (bf16, 3-pass) */
    {
        dim3 g(HID / 128, MB_ / 128);
        gemm_mma<0,3><<<g, 256, GEMM_SMEM>>>(
            (const uint16_t*)pEh, (const uint16_t*)pEl, inputs,
            (const uint16_t*)pW0xh, (const uint16_t*)pW0xl,
            HID, b0, pX0, HID, HID);
    }

    const dim3 gs(32, 8);

    /* layer-0 recurrence */
    for (int t = 0; t < T_SEQ; t++) {
        const __nv_bfloat16* ah = t ? (pH0h + (size_t)(t - 1) * BH) : pHIh;
        const __nv_bfloat16* al = t ? (pH0l + (size_t)(t - 1) * BH) : pHIl;
        rnn_step_mma<<<gs, 256, STEP_SMEM>>>(
            ah, al, pW0hh, pW0hl, pX0 + (size_t)t * BH, pPart,
            (__nv_bfloat162*)(pH0h + (size_t)t * BH),
            (__nv_bfloat162*)(pH0l + (size_t)t * BH),
            (__half2*)0);
    }

    /* X1 = H0 @ W1x^T + b1   (bf16, 3-pass) */
    {
        dim3 g(HID / 128, MB_ / 128);
        gemm_mma<0,3><<<g, 256, GEMM_SMEM>>>(
            (const uint16_t*)pH0h, (const uint16_t*)pH0l, (const void*)0,
            (const uint16_t*)pW1xh, (const uint16_t*)pW1xl,
            HID, b1, pX1, HID, HID);
    }

    /* layer-1 recurrence (emits fp16-hi mirror of H1 for logits) */
    for (int t = 0; t < T_SEQ; t++) {
        const __nv_bfloat16* ah = t ? (pH1h + (size_t)(t - 1) * BH) : (pHIh + BH);
        const __nv_bfloat16* al = t ? (pH1l + (size_t)(t - 1) * BH) : (pHIl + BH);
        rnn_step_mma<<<gs, 256, STEP_SMEM>>>(
            ah, al, pW1hh, pW1hl, pX1 + (size_t)t * BH, pPart,
            (__nv_bfloat162*)(pH1h + (size_t)t * BH),
            (__nv_bfloat162*)(pH1l + (size_t)t * BH),
            (__half2*)(pH1fh + (size_t)t * BH));
    }

    /* logits = H1 @ Wout^T + bout   (fp16, 1-pass: Hh*Wh) */
    {
        dim3 g((VOCAB + 127) / 128, MB_ / 128);
        gemm_mma<1,1><<<g, 256, GEMM_SMEM>>>(
            (const uint16_t*)pH1fh, (const uint16_t*)0, (const void*)0,
            (const uint16_t*)pWof, (const uint16_t*)0,
            VOCAB, bout, out, VOCAB, VOCAB);
    }

    copy_final_hl<<<(BH + 255) / 256, 256>>>(
        (const __nv_bfloat162*)(pH0h + (size_t)(T_SEQ - 1) * BH),
        (const __nv_bfloat162*)(pH0l + (size_t)(T_SEQ - 1) * BH),
        (const __nv_bfloat162*)(pH1h + (size_t)(T_SEQ - 1) * BH),
        (const __nv_bfloat162*)(pH1l + (size_t)(T_SEQ - 1) * BH),
        (float2*)(out + (size_t)MB_ * VOCAB));
}

// round 14
// speedup vs baseline: 1.8350x; 1.0144x over previous
#include <cuda_runtime.h>
#include <cuda_bf16.h>
#include <cuda_fp16.h>
#include <math.h>
#include <stdint.h>

#define T_SEQ 128
#define BATCH 64
#define EMB   2048
#define HID   2048
#define VOCAB 10000
#define MB_   (T_SEQ * BATCH)   /* 8192 */
#define BH    (BATCH * HID)     /* 131072 */

/* ------------------------------------------------------------------ */
/* Scratch (device globals only)                                       */
/* ------------------------------------------------------------------ */
__device__ float g_X0[(size_t)MB_ * HID];
__device__ float g_X1[(size_t)MB_ * HID];
__device__ float g_part[2][8][BH];           /* parity-double-buffered  */
__device__ int   g_cnt2[2][32];
__device__ int   g_flag[32];                 /* steps completed / strip */
__device__ int   g_done;
__device__ int   g_is64;

__device__ __nv_bfloat16 g_emb_hi [(size_t)VOCAB * EMB];
__device__ __nv_bfloat16 g_emb_lo [(size_t)VOCAB * EMB];
__device__ __nv_bfloat16 g_w0x_hi [(size_t)HID * HID];
__device__ __nv_bfloat16 g_w0x_lo [(size_t)HID * HID];
__device__ __nv_bfloat16 g_w0h_hi [(size_t)HID * HID];
__device__ __nv_bfloat16 g_w0h_lo [(size_t)HID * HID];
__device__ __nv_bfloat16 g_w1x_hi [(size_t)HID * HID];
__device__ __nv_bfloat16 g_w1x_lo [(size_t)HID * HID];
__device__ __nv_bfloat16 g_w1h_hi [(size_t)HID * HID];
__device__ __nv_bfloat16 g_w1h_lo [(size_t)HID * HID];
__device__ __half        g_woutf  [(size_t)VOCAB * HID];   /* fp16 hi only */
__device__ __nv_bfloat16 g_H0_hi  [(size_t)MB_ * HID];
__device__ __nv_bfloat16 g_H0_lo  [(size_t)MB_ * HID];
__device__ __nv_bfloat16 g_H1_hi  [(size_t)MB_ * HID];
__device__ __nv_bfloat16 g_H1_lo  [(size_t)MB_ * HID];
__device__ __half        g_H1f_hi [(size_t)MB_ * HID];     /* fp16 mirror  */
__device__ __nv_bfloat16 g_hin_hi [2 * BH];
__device__ __nv_bfloat16 g_hin_lo [2 * BH];

/* ------------------------------------------------------------------ */
__device__ __forceinline__ uint32_t s2u(const void* p) {
    uint32_t a;
    asm("{ .reg .u64 t; cvta.to.shared.u64 t, %1; cvt.u32.u64 %0, t; }"
        : "=r"(a) : "l"(p));
    return a;
}
__device__ __forceinline__ void ldm_x4(uint32_t& r0, uint32_t& r1,
                                       uint32_t& r2, uint32_t& r3, uint32_t a) {
    asm volatile("ldmatrix.sync.aligned.m8n8.x4.shared.b16 {%0,%1,%2,%3}, [%4];"
                 : "=r"(r0), "=r"(r1), "=r"(r2), "=r"(r3) : "r"(a));
}
__device__ __forceinline__ void mma_bf16(float* c, const uint32_t* a,
                                         const uint32_t* b) {
    asm volatile(
        "mma.sync.aligned.m16n8k16.row.col.f32.bf16.bf16.f32 "
        "{%0,%1,%2,%3}, {%4,%5,%6,%7}, {%8,%9}, {%0,%1,%2,%3};"
        : "+f"(c[0]), "+f"(c[1]), "+f"(c[2]), "+f"(c[3])
        : "r"(a[0]), "r"(a[1]), "r"(a[2]), "r"(a[3]), "r"(b[0]), "r"(b[1]));
}
__device__ __forceinline__ void mma_f16(float* c, const uint32_t* a,
                                        const uint32_t* b) {
    asm volatile(
        "mma.sync.aligned.m16n8k16.row.col.f32.f16.f16.f32 "
        "{%0,%1,%2,%3}, {%4,%5,%6,%7}, {%8,%9}, {%0,%1,%2,%3};"
        : "+f"(c[0]), "+f"(c[1]), "+f"(c[2]), "+f"(c[3])
        : "r"(a[0]), "r"(a[1]), "r"(a[2]), "r"(a[3]), "r"(b[0]), "r"(b[1]));
}
__device__ __forceinline__ void cpa16(uint32_t dst, const void* src, int srcsz) {
    asm volatile("cp.async.cg.shared.global [%0], [%1], 16, %2;"
                 :: "r"(dst), "l"(src), "r"(srcsz) : "memory");
}
__device__ __forceinline__ void cpa_commit() {
    asm volatile("cp.async.commit_group;" ::: "memory");
}

/* ------------------------------------------------------------------ */
__global__ void detect_idx_kernel(const unsigned int* __restrict__ p) {
    if (threadIdx.x == 0) {
        unsigned int o = 0;
#pragma unroll
        for (int i = 0; i < 16; i++) o |= p[2 * i + 1];
        g_is64 = (o == 0u) ? 1 : 0;
    }
}

/* ------------------------------------------------------------------ */
/* fp32 -> bf16 hi/lo split                                            */
/* ------------------------------------------------------------------ */
__global__ void conv_split(const float4* __restrict__ src, long n4,
                           int c4s, int ld4s,
                           __nv_bfloat162* __restrict__ hi,
                           __nv_bfloat162* __restrict__ lo)
{
    long i = (long)blockIdx.x * 256 + threadIdx.x;
    if (i >= n4) return;
    long r = i >> c4s;
    long c = i & ((1L << c4s) - 1);
    float4 v = src[(r << ld4s) + c];
    __nv_bfloat16 hx = __float2bfloat16(v.x), hy = __float2bfloat16(v.y);
    __nv_bfloat16 hz = __float2bfloat16(v.z), hw = __float2bfloat16(v.w);
    __nv_bfloat162 h0; h0.x = hx; h0.y = hy;
    __nv_bfloat162 h1; h1.x = hz; h1.y = hw;
    hi[2 * i] = h0; hi[2 * i + 1] = h1;
    __nv_bfloat162 l0, l1;
    l0.x = __float2bfloat16(v.x - __bfloat162float(hx));
    l0.y = __float2bfloat16(v.y - __bfloat162float(hy));
    l1.x = __float2bfloat16(v.z - __bfloat162float(hz));
    l1.y = __float2bfloat16(v.w - __bfloat162float(hw));
    lo[2 * i] = l0; lo[2 * i + 1] = l1;
}

/* fp32 -> fp16 (hi only, for Wout) */
__global__ void conv_f16hi(const float4* __restrict__ src, long n4,
                           __half2* __restrict__ hi)
{
    long i = (long)blockIdx.x * 256 + threadIdx.x;
    if (i >= n4) return;
    float4 v = src[i];
    __half2 h0; h0.x = __float2half(v.x); h0.y = __float2half(v.y);
    __half2 h1; h1.x = __float2half(v.z); h1.y = __float2half(v.w);
    hi[2 * i] = h0; hi[2 * i + 1] = h1;
}

/* ------------------------------------------------------------------ */
/* Big mma.sync GEMM (unchanged R13).                                  */
/* ------------------------------------------------------------------ */
#define ROWB   80
#define R_AHI  0
#define R_ALO  10240
#define R_BHI  20480
#define R_BLO  30720
#define STAGEB 40960
#define NSTG   4
#define GEMM_SMEM (NSTG * STAGEB)   /* 160 KB */

template<int FP16, int PASSES>
__global__ __launch_bounds__(256, 1) void gemm_mma(
    const uint16_t* __restrict__ Ahi, const uint16_t* __restrict__ Alo,
    const void* __restrict__ aidx,
    const uint16_t* __restrict__ Bhi, const uint16_t* __restrict__ Blo,
    int nrowsB, const float* __restrict__ bias,
    float* __restrict__ C, int ldc, int ncols)
{
    extern __shared__ char smem[];
    const uint32_t smbase = s2u(smem);

    const int tid  = threadIdx.x;
    const int lane = tid & 31;
    const int wid  = tid >> 5;
    const int wm   = wid & 3;
    const int wn   = wid >> 2;
    const int bm   = blockIdx.y * 128;
    const int bn   = blockIdx.x * 128;

    const int lrow  = tid >> 1;
    const int cpair = (tid & 1) * 2;
    const uint32_t dstOff = (uint32_t)(lrow * ROWB + cpair * 16);

    size_t aoff;
    {
        const int m = bm + lrow;
        size_t row;
        if (aidx) {
            if (g_is64) row = (size_t)((const long long*)aidx)[m];
            else        row = (size_t)((const int*)aidx)[m];
        } else row = (size_t)m;
        aoff = row * 2048 + (size_t)cpair * 8;
    }
    const int  nrow = bn + lrow;
    const int  bsz  = (nrow < nrowsB) ? 16 : 0;
    const size_t boff = (size_t)((nrow < nrowsB) ? nrow : 0) * 2048
                      + (size_t)cpair * 8;

    const int rlane  = lane & 15;
    const int khalf2 = (lane >> 4) * 16;
    uint32_t rowA[2], rowB[4];
#pragma unroll
    for (int mt = 0; mt < 2; mt++)
        rowA[mt] = (uint32_t)((wm * 32 + mt * 16 + rlane) * ROWB);
#pragma unroll
    for (int nt = 0; nt < 4; nt++)
        rowB[nt] = (uint32_t)((wn * 64 + nt * 16 + rlane) * ROWB);

    float acc[2][8][4];
#pragma unroll
    for (int mt = 0; mt < 2; mt++)
#pragma unroll
        for (int j = 0; j < 8; j++)
#pragma unroll
            for (int q = 0; q < 4; q++) acc[mt][j][q] = 0.f;

    const int NIT = 2048 / 32;

    auto issue = [&](int it) {
        const uint32_t sb = smbase + (uint32_t)(it & (NSTG - 1)) * STAGEB;
        const size_t kb = (size_t)it * 32;
        cpa16(sb + R_AHI + dstOff,      Ahi + aoff + kb,     16);
        cpa16(sb + R_AHI + dstOff + 16, Ahi + aoff + kb + 8, 16);
        if (PASSES >= 2) {
            cpa16(sb + R_ALO + dstOff,      Alo + aoff + kb,     16);
            cpa16(sb + R_ALO + dstOff + 16, Alo + aoff + kb + 8, 16);
        }
        cpa16(sb + R_BHI + dstOff,      Bhi + boff + kb,     bsz);
        cpa16(sb + R_BHI + dstOff + 16, Bhi + boff + kb + 8, bsz);
        if (PASSES == 3) {
            cpa16(sb + R_BLO + dstOff,      Blo + boff + kb,     bsz);
            cpa16(sb + R_BLO + dstOff + 16, Blo + boff + kb + 8, bsz);
        }
        cpa_commit();
    };

    issue(0); issue(1); issue(2);

    for (int it = 0; it < NIT; it++) {
        asm volatile("cp.async.wait_group 2;" ::: "memory");
        __syncthreads();
        if (it + NSTG - 1 < NIT) issue(it + NSTG - 1);
        else                     cpa_commit();

        const uint32_t sb = smbase + (uint32_t)(it & (NSTG - 1)) * STAGEB;
#pragma unroll
        for (int kk = 0; kk < 2; kk++) {
            const uint32_t kbyt = (uint32_t)(kk * 32 + khalf2);
            uint32_t ah[2][4], al[2][4];
#pragma unroll
            for (int mt = 0; mt < 2; mt++) {
                ldm_x4(ah[mt][0], ah[mt][1], ah[mt][2], ah[mt][3],
                       sb + R_AHI + rowA[mt] + kbyt);
                if (PASSES >= 2)
                    ldm_x4(al[mt][0], al[mt][1], al[mt][2], al[mt][3],
                           sb + R_ALO + rowA[mt] + kbyt);
            }
            uint32_t bh[8][2], bl[8][2];
#pragma unroll
            for (int nt = 0; nt < 4; nt++) {
                uint32_t t0, t1, t2, t3;
                ldm_x4(t0, t1, t2, t3, sb + R_BHI + rowB[nt] + kbyt);
                bh[2*nt][0] = t0; bh[2*nt][1] = t2;
                bh[2*nt+1][0] = t1; bh[2*nt+1][1] = t3;
                if (PASSES == 3) {
                    ldm_x4(t0, t1, t2, t3, sb + R_BLO + rowB[nt] + kbyt);
                    bl[2*nt][0] = t0; bl[2*nt][1] = t2;
                    bl[2*nt+1][0] = t1; bl[2*nt+1][1] = t3;
                }
            }
#pragma unroll
            for (int mt = 0; mt < 2; mt++)
#pragma unroll
                for (int j = 0; j < 8; j++) {
                    if (FP16) {
                        mma_f16(acc[mt][j], ah[mt], bh[j]);
                        if (PASSES >= 2) mma_f16(acc[mt][j], al[mt], bh[j]);
                        if (PASSES == 3) mma_f16(acc[mt][j], ah[mt], bl[j]);
                    } else {
                        mma_bf16(acc[mt][j], ah[mt], bh[j]);
                        if (PASSES >= 2) mma_bf16(acc[mt][j], al[mt], bh[j]);
                        if (PASSES == 3) mma_bf16(acc[mt][j], ah[mt], bl[j]);
                    }
                }
        }
    }

    const int gid = lane >> 2;
    const int tig = lane & 3;
#pragma unroll
    for (int mt = 0; mt < 2; mt++) {
#pragma unroll
        for (int j = 0; j < 8; j++) {
            const int col = bn + wn * 64 + j * 8 + tig * 2;
            if (col < ncols) {
                const float bx = bias[col], by = bias[col + 1];
                const size_t r0 = (size_t)(bm + wm * 32 + mt * 16 + gid);
                const size_t r1 = r0 + 8;
                float2 v0 = make_float2(acc[mt][j][0] + bx, acc[mt][j][1] + by);
                float2 v1 = make_float2(acc[mt][j][2] + bx, acc[mt][j][3] + by);
                *(float2*)(C + r0 * (size_t)ldc + col) = v0;
                *(float2*)(C + r1 * (size_t)ldc + col) = v1;
            }
        }
    }
}

/* ------------------------------------------------------------------ */
/* Persistent recurrence: one launch per layer, 256 co-resident CTAs   */
/* (strip 0..31, kslice 0..7) loop over all T_SEQ steps with           */
/* fine-grained per-strip flag sync. Block (s,k) at step t only needs  */
/* strips [4k, 4k+4) of h(t-1). Partials double-buffered by parity.    */
/* ------------------------------------------------------------------ */
#define SROWB  144
#define R2_AH  0
#define R2_AL  9216
#define R2_BH  18432
#define R2_BL  27648
#define STAGE2 36864
#define STEP_SMEM (3 * STAGE2)   /* 108 KB -> 2 CTAs/SM */

__global__ __launch_bounds__(256, 2) void rnn_persist(
    const __nv_bfloat16* __restrict__ hin_hi,
    const __nv_bfloat16* __restrict__ hin_lo,
    const __nv_bfloat16* __restrict__ Whi, const __nv_bfloat16* __restrict__ Wlo,
    const float* __restrict__ Xbase, float* __restrict__ partBase,
    __nv_bfloat16* __restrict__ Hhi, __nv_bfloat16* __restrict__ Hlo,
    __half* __restrict__ H16)
{
    extern __shared__ char smem[];
    __shared__ int s_last;
    const uint32_t smbase = s2u(smem);

    const int tid  = threadIdx.x;
    const int lane = tid & 31;
    const int wid  = tid >> 5;
    const int wm   = wid & 3;
    const int wn   = wid >> 2;
    const int strip  = blockIdx.x;     /* 0..31 */
    const int kslice = blockIdx.y;     /* 0..7  */
    const int kbase0 = kslice * 256;

    const int lrow = tid >> 2;
    const int c0   = (tid & 3) * 2;
    const uint32_t dOff = (uint32_t)(lrow * SROWB + c0 * 16);
    const size_t aO = (size_t)lrow * 2048 + (size_t)c0 * 8;
    const size_t bO = (size_t)(strip * 64 + lrow) * 2048 + (size_t)c0 * 8;

    const int rlane = lane & 15;
    const int khalf = (lane >> 4) * 16;
    const uint32_t arow = (uint32_t)((wm * 16 + rlane) * SROWB);
    uint32_t brow[2];
    brow[0] = (uint32_t)((wn * 32 + rlane) * SROWB);
    brow[1] = (uint32_t)((wn * 32 + 16 + rlane) * SROWB);

    for (int t = 0; t < T_SEQ; t++) {
        const __nv_bfloat16* ah;
        const __nv_bfloat16* al;
        if (t == 0) {
            ah = hin_hi; al = hin_lo;
        } else {
            ah = Hhi + (size_t)(t - 1) * BH;
            al = Hlo + (size_t)(t - 1) * BH;
            /* wait for the 4 A-strips this kslice reads */
            if (tid < 4) {
                volatile int* f = &g_flag[kslice * 4 + tid];
                while (*f < t) __nanosleep(40);
            }
            __syncthreads();
            __threadfence();
        }

        auto issue = [&](int it) {
            const uint32_t sb = smbase + (uint32_t)(it % 3) * STAGE2;
            const size_t kb = (size_t)(kbase0 + it * 64);
            cpa16(sb + R2_AH + dOff,      ah + aO + kb,      16);
            cpa16(sb + R2_AH + dOff + 16, ah + aO + kb + 8,  16);
            cpa16(sb + R2_AL + dOff,      al + aO + kb,      16);
            cpa16(sb + R2_AL + dOff + 16, al + aO + kb + 8,  16);
            cpa16(sb + R2_BH + dOff,      Whi + bO + kb,     16);
            cpa16(sb + R2_BH + dOff + 16, Whi + bO + kb + 8, 16);
            cpa16(sb + R2_BL + dOff,      Wlo + bO + kb,     16);
            cpa16(sb + R2_BL + dOff + 16, Wlo + bO + kb + 8, 16);
            cpa_commit();
        };

        float acc[4][4];
#pragma unroll
        for (int j = 0; j < 4; j++)
#pragma unroll
            for (int q = 0; q < 4; q++) acc[j][q] = 0.f;

        issue(0); issue(1);

        for (int it = 0; it < 4; it++) {
            asm volatile("cp.async.wait_group 1;" ::: "memory");
            __syncthreads();
            if (it + 2 < 4) issue(it + 2);
            else            cpa_commit();

            const uint32_t sb = smbase + (uint32_t)(it % 3) * STAGE2;
#pragma unroll
            for (int kk = 0; kk < 4; kk++) {
                const uint32_t kbyt = (uint32_t)(kk * 32 + khalf);
                uint32_t ahr[4], alr[4];
                ldm_x4(ahr[0], ahr[1], ahr[2], ahr[3], sb + R2_AH + arow + kbyt);
                ldm_x4(alr[0], alr[1], alr[2], alr[3], sb + R2_AL + arow + kbyt);
                uint32_t bh[4][2], bl[4][2];
#pragma unroll
                for (int nt = 0; nt < 2; nt++) {
                    uint32_t t0, t1, t2, t3;
                    ldm_x4(t0, t1, t2, t3, sb + R2_BH + brow[nt] + kbyt);
                    bh[2*nt][0] = t0; bh[2*nt][1] = t2;
                    bh[2*nt+1][0] = t1; bh[2*nt+1][1] = t3;
                    ldm_x4(t0, t1, t2, t3, sb + R2_BL + brow[nt] + kbyt);
                    bl[2*nt][0] = t0; bl[2*nt][1] = t2;
                    bl[2*nt+1][0] = t1; bl[2*nt+1][1] = t3;
                }
#pragma unroll
                for (int j = 0; j < 4; j++) {
                    mma_bf16(acc[j], ahr, bh[j]);
                    mma_bf16(acc[j], ahr, bl[j]);
                    mma_bf16(acc[j], alr, bh[j]);
                }
            }
        }

        /* partial write (parity buffer) */
        float* dst = partBase + (size_t)(t & 1) * (8 * (size_t)BH)
                   + (size_t)kslice * BH;
        const int r0 = wm * 16 + (lane >> 2);
#pragma unroll
        for (int j = 0; j < 4; j++) {
            const int col = strip * 64 + wn * 32 + j * 8 + (lane & 3) * 2;
            *(float2*)(dst + (size_t)r0 * 2048 + col) =
                make_float2(acc[j][0], acc[j][1]);
            *(float2*)(dst + (size_t)(r0 + 8) * 2048 + col) =
                make_float2(acc[j][2], acc[j][3]);
        }

        __threadfence();
        if (tid == 0) {
            int old = atomicAdd(&g_cnt2[t & 1][strip], 1);
            s_last = (old == 7) ? 1 : 0;
        }
        __syncthreads();

        if (s_last) {
            __threadfence();
            const float4* p4 = (const float4*)(partBase
                               + (size_t)(t & 1) * (8 * (size_t)BH));
            const float4* x4 = (const float4*)(Xbase + (size_t)t * BH);
            __nv_bfloat162* oHi = (__nv_bfloat162*)(Hhi + (size_t)t * BH);
            __nv_bfloat162* oLo = (__nv_bfloat162*)(Hlo + (size_t)t * BH);
            __half2* o16 = H16 ? (__half2*)(H16 + (size_t)t * BH) : (__half2*)0;

            for (int u = tid; u < 1024; u += 256) {
                const int m  = u >> 4;
                const int c4 = u & 15;
                const size_t off = (size_t)m * 512 + (size_t)strip * 16 + c4;
                float4 sv = p4[off];
#pragma unroll
                for (int kg = 1; kg < 8; kg++) {
                    float4 p = p4[(size_t)kg * (BH / 4) + off];
                    sv.x += p.x; sv.y += p.y; sv.z += p.z; sv.w += p.w;
                }
                float4 xv = x4[off];
                sv.x = tanhf(sv.x + xv.x); sv.y = tanhf(sv.y + xv.y);
                sv.z = tanhf(sv.z + xv.z); sv.w = tanhf(sv.w + xv.w);

                __nv_bfloat16 hx = __float2bfloat16(sv.x);
                __nv_bfloat16 hy = __float2bfloat16(sv.y);
                __nv_bfloat16 hz = __float2bfloat16(sv.z);
                __nv_bfloat16 hw = __float2bfloat16(sv.w);
                __nv_bfloat162 a; a.x = hx; a.y = hy;
                __nv_bfloat162 b; b.x = hz; b.y = hw;
                oHi[2 * off] = a; oHi[2 * off + 1] = b;
                __nv_bfloat162 la, lb;
                la.x = __float2bfloat16(sv.x - __bfloat162float(hx));
                la.y = __float2bfloat16(sv.y - __bfloat162float(hy));
                lb.x = __float2bfloat16(sv.z - __bfloat162float(hz));
                lb.y = __float2bfloat16(sv.w - __bfloat162float(hw));
                oLo[2 * off] = la; oLo[2 * off + 1] = lb;

                if (o16) {
                    __half2 fa; fa.x = __float2half(sv.x); fa.y = __float2half(sv.y);
                    __half2 fb; fb.x = __float2half(sv.z); fb.y = __float2half(sv.w);
                    o16[2 * off] = fa; o16[2 * off + 1] = fb;
                }
            }
            __threadfence();
            __syncthreads();
            if (tid == 0) {
                g_cnt2[t & 1][strip] = 0;
                atomicExch(&g_flag[strip], t + 1);
            }
        }
    }

    /* self-reset for the next launch / graph replay */
    __threadfence();
    __syncthreads();
    if (tid == 0) {
        int old = atomicAdd(&g_done, 1);
        if (old == 255) {
#pragma unroll
            for (int s = 0; s < 32; s++) g_flag[s] = 0;
            __threadfence();
            g_done = 0;
        }
    }
}

/* ------------------------------------------------------------------ */
__global__ void copy_final_hl(
    const __nv_bfloat162* __restrict__ h0h, const __nv_bfloat162* __restrict__ h0l,
    const __nv_bfloat162* __restrict__ h1h, const __nv_bfloat162* __restrict__ h1l,
    float2* __restrict__ out)
{
    const int i = blockIdx.x * 256 + threadIdx.x;
    if (i >= BH) return;
    const __nv_bfloat162 h = (i < BH / 2) ? h0h[i] : h1h[i - BH / 2];
    const __nv_bfloat162 l = (i < BH / 2) ? h0l[i] : h1l[i - BH / 2];
    float2 v;
    v.x = __bfloat162float(h.x) + __bfloat162float(l.x);
    v.y = __bfloat162float(h.y) + __bfloat162float(l.y);
    out[i] = v;
}

/* ------------------------------------------------------------------ */
extern "C" void kernel_launch(void* const* d_in, const int* in_sizes, int n_in,
                              void* d_out, int out_size)
{
    (void)in_sizes; (void)n_in; (void)out_size;

    const void*  inputs = d_in[0];
    const float* hidden = (const float*)d_in[1];
    const float* emb    = (const float*)d_in[2];
    const float* W0     = (const float*)d_in[3];
    const float* b0     = (const float*)d_in[4];
    const float* W1     = (const float*)d_in[5];
    const float* b1     = (const float*)d_in[6];
    const float* Wout   = (const float*)d_in[7];
    const float* bout   = (const float*)d_in[8];
    float* out = (float*)d_out;

    float *pX0, *pX1, *pPart;
    __nv_bfloat16 *pEh, *pEl, *pW0xh, *pW0xl, *pW0hh, *pW0hl;
    __nv_bfloat16 *pW1xh, *pW1xl, *pW1hh, *pW1hl;
    __nv_bfloat16 *pH0h, *pH0l, *pH1h, *pH1l, *pHIh, *pHIl;
    __half *pWof, *pH1fh;
    cudaGetSymbolAddress((void**)&pX0,   g_X0);
    cudaGetSymbolAddress((void**)&pX1,   g_X1);
    cudaGetSymbolAddress((void**)&pPart, g_part);
    cudaGetSymbolAddress((void**)&pEh,   g_emb_hi);
    cudaGetSymbolAddress((void**)&pEl,   g_emb_lo);
    cudaGetSymbolAddress((void**)&pW0xh, g_w0x_hi);
    cudaGetSymbolAddress((void**)&pW0xl, g_w0x_lo);
    cudaGetSymbolAddress((void**)&pW0hh, g_w0h_hi);
    cudaGetSymbolAddress((void**)&pW0hl, g_w0h_lo);
    cudaGetSymbolAddress((void**)&pW1xh, g_w1x_hi);
    cudaGetSymbolAddress((void**)&pW1xl, g_w1x_lo);
    cudaGetSymbolAddress((void**)&pW1hh, g_w1h_hi);
    cudaGetSymbolAddress((void**)&pW1hl, g_w1h_lo);
    cudaGetSymbolAddress((void**)&pWof,  g_woutf);
    cudaGetSymbolAddress((void**)&pH0h,  g_H0_hi);
    cudaGetSymbolAddress((void**)&pH0l,  g_H0_lo);
    cudaGetSymbolAddress((void**)&pH1h,  g_H1_hi);
    cudaGetSymbolAddress((void**)&pH1l,  g_H1_lo);
    cudaGetSymbolAddress((void**)&pH1fh, g_H1f_hi);
    cudaGetSymbolAddress((void**)&pHIh,  g_hin_hi);
    cudaGetSymbolAddress((void**)&pHIl,  g_hin_lo);

    static int smem_set = 0;
    if (!smem_set) {
        cudaFuncSetAttribute(gemm_mma<0,3>,
                             cudaFuncAttributeMaxDynamicSharedMemorySize, GEMM_SMEM);
        cudaFuncSetAttribute(gemm_mma<1,1>,
                             cudaFuncAttributeMaxDynamicSharedMemorySize, GEMM_SMEM);
        cudaFuncSetAttribute(rnn_persist,
                             cudaFuncAttributeMaxDynamicSharedMemorySize, STEP_SMEM);
        smem_set = 1;
    }

    detect_idx_kernel<<<1, 32>>>((const unsigned int*)inputs);

    /* hi/lo conversions */
    {
        long n4;
        n4 = (long)VOCAB * (EMB / 4);
        conv_split<<<(unsigned)((n4 + 255) / 256), 256>>>(
            (const float4*)emb, n4, 9, 9, (__nv_bfloat162*)pEh, (__nv_bfloat162*)pEl);
        n4 = (long)VOCAB * (HID / 4);
        conv_f16hi<<<(unsigned)((n4 + 255) / 256), 256>>>(
            (const float4*)Wout, n4, (__half2*)pWof);
        n4 = (long)HID * (HID / 4);
        conv_split<<<(unsigned)((n4 + 255) / 256), 256>>>(
            (const float4*)W0, n4, 9, 10,
            (__nv_bfloat162*)pW0xh, (__nv_bfloat162*)pW0xl);
        conv_split<<<(unsigned)((n4 + 255) / 256), 256>>>(
            (const float4*)(W0 + 2048), n4, 9, 10,
            (__nv_bfloat162*)pW0hh, (__nv_bfloat162*)pW0hl);
        conv_split<<<(unsigned)((n4 + 255) / 256), 256>>>(
            (const float4*)W1, n4, 9, 10,
            (__nv_bfloat162*)pW1xh, (__nv_bfloat162*)pW1xl);
        conv_split<<<(unsigned)((n4 + 255) / 256), 256>>>(
            (const float4*)(W1 + 2048), n4, 9, 10,
            (__nv_bfloat162*)pW1hh, (__nv_bfloat162*)pW1hl);
        n4 = (long)(2 * BH) / 4;
        conv_split<<<(unsigned)((n4 + 255) / 256), 256>>>(
            (const float4*)hidden, n4, 9, 9,
            (__nv_bfloat162*)pHIh, (__nv_bfloat162*)pHIl);
    }

    /* X0 = emb[inputs] @ W0x^T + b0   (bf16, 3-pass) */
    {
        dim3 g(HID / 128, MB_ / 128);
        gemm_mma<0,3><<<g, 256, GEMM_SMEM>>>(
            (const uint16_t*)pEh, (const uint16_t*)pEl, inputs,
            (const uint16_t*)pW0xh, (const uint16_t*)pW0xl,
            HID, b0, pX0, HID, HID);
    }

    const dim3 gs(32, 8);

    /* layer-0 recurrence: ONE persistent launch */
    rnn_persist<<<gs, 256, STEP_SMEM>>>(
        pHIh, pHIl, pW0hh, pW0hl, pX0, pPart,
        pH0h, pH0l, (__half*)0);

    /* X1 = H0 @ W1x^T + b1   (bf16, 3-pass) */
    {
        dim3 g(HID / 128, MB_ / 128);
        gemm_mma<0,3><<<g, 256, GEMM_SMEM>>>(
            (const uint16_t*)pH0h, (const uint16_t*)pH0l, (const void*)0,
            (const uint16_t*)pW1xh, (const uint16_t*)pW1xl,
            HID, b1, pX1, HID, HID);
    }

    /* layer-1 recurrence: ONE persistent launch (emits fp16 mirror) */
    rnn_persist<<<gs, 256, STEP_SMEM>>>(
        pHIh + BH, pHIl + BH, pW1hh, pW1hl, pX1, pPart,
        pH1h, pH1l, pH1fh);

    /* logits = H1 @ Wout^T + bout   (fp16, 1-pass) */
    {
        dim3 g((VOCAB + 127) / 128, MB_ / 128);
        gemm_mma<1,1><<<g, 256, GEMM_SMEM>>>(
            (const uint16_t*)pH1fh, (const uint16_t*)0, (const void*)0,
            (const uint16_t*)pWof, (const uint16_t*)0,
            VOCAB, bout, out, VOCAB, VOCAB);
    }

    copy_final_hl<<<(BH + 255) / 256, 256>>>(
        (const __nv_bfloat162*)(pH0h + (size_t)(T_SEQ - 1) * BH),
        (const __nv_bfloat162*)(pH0l + (size_t)(T_SEQ - 1) * BH),
        (const __nv_bfloat162*)(pH1h + (size_t)(T_SEQ - 1) * BH),
        (const __nv_bfloat162*)(pH1l + (size_t)(T_SEQ - 1) * BH),
        (float2*)(out + (size_t)MB_ * VOCAB));
}

// round 15
// speedup vs baseline: 2.0173x; 1.0993x over previous
#include <cuda_runtime.h>
#include <cuda_bf16.h>
#include <cuda_fp16.h>
#include <math.h>
#include <stdint.h>

#define T_SEQ 128
#define BATCH 64
#define EMB   2048
#define HID   2048
#define VOCAB 10000
#define MB_   (T_SEQ * BATCH)   /* 8192 */
#define BH    (BATCH * HID)     /* 131072 */

/* ------------------------------------------------------------------ */
/* Scratch (device globals only)                                       */
/* ------------------------------------------------------------------ */
__device__ float g_X0[(size_t)MB_ * HID];
__device__ float g_X1[(size_t)MB_ * HID];
__device__ float g_part[2][8][BH];           /* parity-double-buffered  */
__device__ int   g_cnt2[2][32];
__device__ int   g_flag[32];                 /* steps completed / strip */
__device__ int   g_done;
__device__ int   g_is64;

__device__ __nv_bfloat16 g_emb_hi [(size_t)VOCAB * EMB];
__device__ __nv_bfloat16 g_emb_lo [(size_t)VOCAB * EMB];
__device__ __nv_bfloat16 g_w0x_hi [(size_t)HID * HID];
__device__ __nv_bfloat16 g_w0x_lo [(size_t)HID * HID];
__device__ __nv_bfloat16 g_w0h_hi [(size_t)HID * HID];
__device__ __nv_bfloat16 g_w0h_lo [(size_t)HID * HID];
__device__ __nv_bfloat16 g_w1x_hi [(size_t)HID * HID];
__device__ __nv_bfloat16 g_w1x_lo [(size_t)HID * HID];
__device__ __nv_bfloat16 g_w1h_hi [(size_t)HID * HID];
__device__ __nv_bfloat16 g_w1h_lo [(size_t)HID * HID];
__device__ __half        g_woutf  [(size_t)VOCAB * HID];   /* fp16 hi only */
__device__ __nv_bfloat16 g_H0_hi  [(size_t)MB_ * HID];
__device__ __nv_bfloat16 g_H0_lo  [(size_t)MB_ * HID];
__device__ __nv_bfloat16 g_H1_hi  [(size_t)MB_ * HID];
__device__ __nv_bfloat16 g_H1_lo  [(size_t)MB_ * HID];
__device__ __half        g_H1f_hi [(size_t)MB_ * HID];     /* fp16 mirror  */
__device__ __nv_bfloat16 g_hin_hi [2 * BH];
__device__ __nv_bfloat16 g_hin_lo [2 * BH];

/* ------------------------------------------------------------------ */
__device__ __forceinline__ uint32_t s2u(const void* p) {
    uint32_t a;
    asm("{ .reg .u64 t; cvta.to.shared.u64 t, %1; cvt.u32.u64 %0, t; }"
        : "=r"(a) : "l"(p));
    return a;
}
__device__ __forceinline__ void ldm_x4(uint32_t& r0, uint32_t& r1,
                                       uint32_t& r2, uint32_t& r3, uint32_t a) {
    asm volatile("ldmatrix.sync.aligned.m8n8.x4.shared.b16 {%0,%1,%2,%3}, [%4];"
                 : "=r"(r0), "=r"(r1), "=r"(r2), "=r"(r3) : "r"(a));
}
__device__ __forceinline__ void mma_bf16(float* c, const uint32_t* a,
                                         const uint32_t* b) {
    asm volatile(
        "mma.sync.aligned.m16n8k16.row.col.f32.bf16.bf16.f32 "
        "{%0,%1,%2,%3}, {%4,%5,%6,%7}, {%8,%9}, {%0,%1,%2,%3};"
        : "+f"(c[0]), "+f"(c[1]), "+f"(c[2]), "+f"(c[3])
        : "r"(a[0]), "r"(a[1]), "r"(a[2]), "r"(a[3]), "r"(b[0]), "r"(b[1]));
}
__device__ __forceinline__ void mma_f16(float* c, const uint32_t* a,
                                        const uint32_t* b) {
    asm volatile(
        "mma.sync.aligned.m16n8k16.row.col.f32.f16.f16.f32 "
        "{%0,%1,%2,%3}, {%4,%5,%6,%7}, {%8,%9}, {%0,%1,%2,%3};"
        : "+f"(c[0]), "+f"(c[1]), "+f"(c[2]), "+f"(c[3])
        : "r"(a[0]), "r"(a[1]), "r"(a[2]), "r"(a[3]), "r"(b[0]), "r"(b[1]));
}
__device__ __forceinline__ void cpa16(uint32_t dst, const void* src, int srcsz) {
    asm volatile("cp.async.cg.shared.global [%0], [%1], 16, %2;"
                 :: "r"(dst), "l"(src), "r"(srcsz) : "memory");
}
__device__ __forceinline__ void cpa_commit() {
    asm volatile("cp.async.commit_group;" ::: "memory");
}

/* ------------------------------------------------------------------ */
__global__ void detect_idx_kernel(const unsigned int* __restrict__ p) {
    if (threadIdx.x == 0) {
        unsigned int o = 0;
#pragma unroll
        for (int i = 0; i < 16; i++) o |= p[2 * i + 1];
        g_is64 = (o == 0u) ? 1 : 0;
    }
}

/* ------------------------------------------------------------------ */
/* fp32 -> bf16 hi/lo split                                            */
/* ------------------------------------------------------------------ */
__global__ void conv_split(const float4* __restrict__ src, long n4,
                           int c4s, int ld4s,
                           __nv_bfloat162* __restrict__ hi,
                           __nv_bfloat162* __restrict__ lo)
{
    long i = (long)blockIdx.x * 256 + threadIdx.x;
    if (i >= n4) return;
    long r = i >> c4s;
    long c = i & ((1L << c4s) - 1);
    float4 v = src[(r << ld4s) + c];
    __nv_bfloat16 hx = __float2bfloat16(v.x), hy = __float2bfloat16(v.y);
    __nv_bfloat16 hz = __float2bfloat16(v.z), hw = __float2bfloat16(v.w);
    __nv_bfloat162 h0; h0.x = hx; h0.y = hy;
    __nv_bfloat162 h1; h1.x = hz; h1.y = hw;
    hi[2 * i] = h0; hi[2 * i + 1] = h1;
    __nv_bfloat162 l0, l1;
    l0.x = __float2bfloat16(v.x - __bfloat162float(hx));
    l0.y = __float2bfloat16(v.y - __bfloat162float(hy));
    l1.x = __float2bfloat16(v.z - __bfloat162float(hz));
    l1.y = __float2bfloat16(v.w - __bfloat162float(hw));
    lo[2 * i] = l0; lo[2 * i + 1] = l1;
}

/* fp32 -> fp16 (hi only, for Wout) */
__global__ void conv_f16hi(const float4* __restrict__ src, long n4,
                           __half2* __restrict__ hi)
{
    long i = (long)blockIdx.x * 256 + threadIdx.x;
    if (i >= n4) return;
    float4 v = src[i];
    __half2 h0; h0.x = __float2half(v.x); h0.y = __float2half(v.y);
    __half2 h1; h1.x = __float2half(v.z); h1.y = __float2half(v.w);
    hi[2 * i] = h0; hi[2 * i + 1] = h1;
}

/* ------------------------------------------------------------------ */
/* Big mma.sync GEMM. Stage layout + occupancy parameterized by        */
/* PASSES: 3 -> 40KB stage, 1 CTA/SM; 1 -> 20KB stage, 2 CTAs/SM.      */
/* ------------------------------------------------------------------ */
#define ROWB   80
#define NSTG   4

template<int FP16, int PASSES>
__global__ __launch_bounds__(256, (PASSES == 1) ? 2 : 1) void gemm_mma(
    const uint16_t* __restrict__ Ahi, const uint16_t* __restrict__ Alo,
    const void* __restrict__ aidx,
    const uint16_t* __restrict__ Bhi, const uint16_t* __restrict__ Blo,
    int nrowsB, const float* __restrict__ bias,
    float* __restrict__ C, int ldc, int ncols)
{
    constexpr uint32_t R_AHI = 0;
    constexpr uint32_t R_ALO = 10240;                       /* if PASSES>=2 */
    constexpr uint32_t R_BHI = (PASSES >= 2) ? 20480u : 10240u;
    constexpr uint32_t R_BLO = 30720;                       /* if PASSES==3 */
    constexpr uint32_t STAGEB = (PASSES == 3) ? 40960u
                              : (PASSES == 2) ? 30720u : 20480u;

    extern __shared__ char smem[];
    const uint32_t smbase = s2u(smem);

    const int tid  = threadIdx.x;
    const int lane = tid & 31;
    const int wid  = tid >> 5;
    const int wm   = wid & 3;
    const int wn   = wid >> 2;
    const int bm   = blockIdx.y * 128;
    const int bn   = blockIdx.x * 128;

    const int lrow  = tid >> 1;
    const int cpair = (tid & 1) * 2;
    const uint32_t dstOff = (uint32_t)(lrow * ROWB + cpair * 16);

    size_t aoff;
    {
        const int m = bm + lrow;
        size_t row;
        if (aidx) {
            if (g_is64) row = (size_t)((const long long*)aidx)[m];
            else        row = (size_t)((const int*)aidx)[m];
        } else row = (size_t)m;
        aoff = row * 2048 + (size_t)cpair * 8;
    }
    const int  nrow = bn + lrow;
    const int  bsz  = (nrow < nrowsB) ? 16 : 0;
    const size_t boff = (size_t)((nrow < nrowsB) ? nrow : 0) * 2048
                      + (size_t)cpair * 8;

    const int rlane  = lane & 15;
    const int khalf2 = (lane >> 4) * 16;
    uint32_t rowA[2], rowB[4];
#pragma unroll
    for (int mt = 0; mt < 2; mt++)
        rowA[mt] = (uint32_t)((wm * 32 + mt * 16 + rlane) * ROWB);
#pragma unroll
    for (int nt = 0; nt < 4; nt++)
        rowB[nt] = (uint32_t)((wn * 64 + nt * 16 + rlane) * ROWB);

    float acc[2][8][4];
#pragma unroll
    for (int mt = 0; mt < 2; mt++)
#pragma unroll
        for (int j = 0; j < 8; j++)
#pragma unroll
            for (int q = 0; q < 4; q++) acc[mt][j][q] = 0.f;

    const int NIT = 2048 / 32;

    auto issue = [&](int it) {
        const uint32_t sb = smbase + (uint32_t)(it & (NSTG - 1)) * STAGEB;
        const size_t kb = (size_t)it * 32;
        cpa16(sb + R_AHI + dstOff,      Ahi + aoff + kb,     16);
        cpa16(sb + R_AHI + dstOff + 16, Ahi + aoff + kb + 8, 16);
        if (PASSES >= 2) {
            cpa16(sb + R_ALO + dstOff,      Alo + aoff + kb,     16);
            cpa16(sb + R_ALO + dstOff + 16, Alo + aoff + kb + 8, 16);
        }
        cpa16(sb + R_BHI + dstOff,      Bhi + boff + kb,     bsz);
        cpa16(sb + R_BHI + dstOff + 16, Bhi + boff + kb + 8, bsz);
        if (PASSES == 3) {
            cpa16(sb + R_BLO + dstOff,      Blo + boff + kb,     bsz);
            cpa16(sb + R_BLO + dstOff + 16, Blo + boff + kb + 8, bsz);
        }
        cpa_commit();
    };

    issue(0); issue(1); issue(2);

    for (int it = 0; it < NIT; it++) {
        asm volatile("cp.async.wait_group 2;" ::: "memory");
        __syncthreads();
        if (it + NSTG - 1 < NIT) issue(it + NSTG - 1);
        else                     cpa_commit();

        const uint32_t sb = smbase + (uint32_t)(it & (NSTG - 1)) * STAGEB;
#pragma unroll
        for (int kk = 0; kk < 2; kk++) {
            const uint32_t kbyt = (uint32_t)(kk * 32 + khalf2);
            uint32_t ah[2][4], al[2][4];
#pragma unroll
            for (int mt = 0; mt < 2; mt++) {
                ldm_x4(ah[mt][0], ah[mt][1], ah[mt][2], ah[mt][3],
                       sb + R_AHI + rowA[mt] + kbyt);
                if (PASSES >= 2)
                    ldm_x4(al[mt][0], al[mt][1], al[mt][2], al[mt][3],
                           sb + R_ALO + rowA[mt] + kbyt);
            }
            uint32_t bh[8][2], bl[8][2];
#pragma unroll
            for (int nt = 0; nt < 4; nt++) {
                uint32_t t0, t1, t2, t3;
                ldm_x4(t0, t1, t2, t3, sb + R_BHI + rowB[nt] + kbyt);
                bh[2*nt][0] = t0; bh[2*nt][1] = t2;
                bh[2*nt+1][0] = t1; bh[2*nt+1][1] = t3;
                if (PASSES == 3) {
                    ldm_x4(t0, t1, t2, t3, sb + R_BLO + rowB[nt] + kbyt);
                    bl[2*nt][0] = t0; bl[2*nt][1] = t2;
                    bl[2*nt+1][0] = t1; bl[2*nt+1][1] = t3;
                }
            }
#pragma unroll
            for (int mt = 0; mt < 2; mt++)
#pragma unroll
                for (int j = 0; j < 8; j++) {
                    if (FP16) {
                        mma_f16(acc[mt][j], ah[mt], bh[j]);
                        if (PASSES >= 2) mma_f16(acc[mt][j], al[mt], bh[j]);
                        if (PASSES == 3) mma_f16(acc[mt][j], ah[mt], bl[j]);
                    } else {
                        mma_bf16(acc[mt][j], ah[mt], bh[j]);
                        if (PASSES >= 2) mma_bf16(acc[mt][j], al[mt], bh[j]);
                        if (PASSES == 3) mma_bf16(acc[mt][j], ah[mt], bl[j]);
                    }
                }
        }
    }

    const int gid = lane >> 2;
    const int tig = lane & 3;
#pragma unroll
    for (int mt = 0; mt < 2; mt++) {
#pragma unroll
        for (int j = 0; j < 8; j++) {
            const int col = bn + wn * 64 + j * 8 + tig * 2;
            if (col < ncols) {
                const float bx = bias[col], by = bias[col + 1];
                const size_t r0 = (size_t)(bm + wm * 32 + mt * 16 + gid);
                const size_t r1 = r0 + 8;
                float2 v0 = make_float2(acc[mt][j][0] + bx, acc[mt][j][1] + by);
                float2 v1 = make_float2(acc[mt][j][2] + bx, acc[mt][j][3] + by);
                *(float2*)(C + r0 * (size_t)ldc + col) = v0;
                *(float2*)(C + r1 * (size_t)ldc + col) = v1;
            }
        }
    }
}

#define GEMM3_SMEM (NSTG * 40960)   /* 160 KB */
#define GEMM1_SMEM (NSTG * 20480)   /*  80 KB */

/* ------------------------------------------------------------------ */
/* Persistent recurrence, WEIGHT-RESIDENT:                             */
/* W slice (64 n-rows x 256 k, hi+lo) loaded to smem ONCE at 528B      */
/* padded stride (conflict-free ldmatrix), reused for all 128 steps.   */
/* Per step only A (h(t-1)) streams through a 2-stage buffer.          */
/* Flag/reduction protocol identical to R14 (proven).                  */
/* ------------------------------------------------------------------ */
#define WROWB   528
#define RW_H    0
#define RW_L    33792
#define RA_BASE 67584
#define RA_ST   18432          /* per stage: A-hi 9216 + A-lo 9216 */
#define SROWB   144
#define STEP_SMEM (RA_BASE + 2 * RA_ST)   /* 104448 B -> 2 CTAs/SM */

__global__ __launch_bounds__(256, 2) void rnn_persist(
    const __nv_bfloat16* __restrict__ hin_hi,
    const __nv_bfloat16* __restrict__ hin_lo,
    const __nv_bfloat16* __restrict__ Whi, const __nv_bfloat16* __restrict__ Wlo,
    const float* __restrict__ Xbase, float* __restrict__ partBase,
    __nv_bfloat16* __restrict__ Hhi, __nv_bfloat16* __restrict__ Hlo,
    __half* __restrict__ H16)
{
    extern __shared__ char smem[];
    __shared__ int s_last;
    const uint32_t smbase = s2u(smem);

    const int tid  = threadIdx.x;
    const int lane = tid & 31;
    const int wid  = tid >> 5;
    const int wm   = wid & 3;
    const int wn   = wid >> 2;
    const int strip  = blockIdx.x;     /* 0..31 */
    const int kslice = blockIdx.y;     /* 0..7  */
    const int kbase0 = kslice * 256;

    /* ---- one-time W slice load: 64 rows x 512B, hi+lo ---- */
    {
        const int wrow = tid >> 2;     /* 0..63 */
        const int wc0  = tid & 3;
        const size_t wO = (size_t)(strip * 64 + wrow) * 2048 + kbase0;
        for (int c = wc0; c < 32; c += 4) {
            cpa16(smbase + RW_H + (uint32_t)(wrow * WROWB + c * 16),
                  Whi + wO + c * 8, 16);
            cpa16(smbase + RW_L + (uint32_t)(wrow * WROWB + c * 16),
                  Wlo + wO + c * 8, 16);
        }
        cpa_commit();
        asm volatile("cp.async.wait_group 0;" ::: "memory");
        __syncthreads();
    }

    /* A loader: 4 threads/row, 32B each per array */
    const int lrow = tid >> 2;
    const int c0   = tid & 3;
    const uint32_t dOff = (uint32_t)(lrow * SROWB + c0 * 32);
    const size_t aO = (size_t)lrow * 2048 + (size_t)c0 * 16;

    const int rlane = lane & 15;
    const int khalf = (lane >> 4) * 16;
    const uint32_t arow = (uint32_t)((wm * 16 + rlane) * SROWB);
    uint32_t browW[2];
    browW[0] = (uint32_t)((wn * 32 + rlane) * WROWB);
    browW[1] = (uint32_t)((wn * 32 + 16 + rlane) * WROWB);

    for (int t = 0; t < T_SEQ; t++) {
        const __nv_bfloat16* ah;
        const __nv_bfloat16* al;
        if (t == 0) {
            ah = hin_hi; al = hin_lo;
        } else {
            ah = Hhi + (size_t)(t - 1) * BH;
            al = Hlo + (size_t)(t - 1) * BH;
            if (tid < 4) {
                volatile int* f = &g_flag[kslice * 4 + tid];
                while (*f < t) __nanosleep(40);
            }
            __syncthreads();
            __threadfence();
        }

        auto issueA = [&](int it) {
            const uint32_t sb = smbase + RA_BASE + (uint32_t)(it & 1) * RA_ST;
            const size_t kb = (size_t)(kbase0 + it * 64);
            cpa16(sb + dOff,             ah + aO + kb,     16);
            cpa16(sb + dOff + 16,        ah + aO + kb + 8, 16);
            cpa16(sb + 9216 + dOff,      al + aO + kb,     16);
            cpa16(sb + 9216 + dOff + 16, al + aO + kb + 8, 16);
            cpa_commit();
        };

        float acc[4][4];
#pragma unroll
        for (int j = 0; j < 4; j++)
#pragma unroll
            for (int q = 0; q < 4; q++) acc[j][q] = 0.f;

        issueA(0);

        for (int it = 0; it < 4; it++) {
            if (it + 1 < 4) {
                issueA(it + 1);
                asm volatile("cp.async.wait_group 1;" ::: "memory");
            } else {
                asm volatile("cp.async.wait_group 0;" ::: "memory");
            }
            __syncthreads();

            const uint32_t sb = smbase + RA_BASE + (uint32_t)(it & 1) * RA_ST;
#pragma unroll
            for (int kk = 0; kk < 4; kk++) {
                const uint32_t kbyt  = (uint32_t)(kk * 32 + khalf);
                const uint32_t kbytW = (uint32_t)(it * 128 + kk * 32 + khalf);
                uint32_t ahr[4], alr[4];
                ldm_x4(ahr[0], ahr[1], ahr[2], ahr[3], sb + arow + kbyt);
                ldm_x4(alr[0], alr[1], alr[2], alr[3], sb + 9216 + arow + kbyt);
                uint32_t bh[4][2], bl[4][2];
#pragma unroll
                for (int nt = 0; nt < 2; nt++) {
                    uint32_t t0, t1, t2, t3;
                    ldm_x4(t0, t1, t2, t3, smbase + RW_H + browW[nt] + kbytW);
                    bh[2*nt][0] = t0; bh[2*nt][1] = t2;
                    bh[2*nt+1][0] = t1; bh[2*nt+1][1] = t3;
                    ldm_x4(t0, t1, t2, t3, smbase + RW_L + browW[nt] + kbytW);
                    bl[2*nt][0] = t0; bl[2*nt][1] = t2;
                    bl[2*nt+1][0] = t1; bl[2*nt+1][1] = t3;
                }
#pragma unroll
                for (int j = 0; j < 4; j++) {
                    mma_bf16(acc[j], ahr, bh[j]);
                    mma_bf16(acc[j], ahr, bl[j]);
                    mma_bf16(acc[j], alr, bh[j]);
                }
            }
            __syncthreads();
        }

        /* partial write (parity buffer) */
        float* dst = partBase + (size_t)(t & 1) * (8 * (size_t)BH)
                   + (size_t)kslice * BH;
        const int r0 = wm * 16 + (lane >> 2);
#pragma unroll
        for (int j = 0; j < 4; j++) {
            const int col = strip * 64 + wn * 32 + j * 8 + (lane & 3) * 2;
            *(float2*)(dst + (size_t)r0 * 2048 + col) =
                make_float2(acc[j][0], acc[j][1]);
            *(float2*)(dst + (size_t)(r0 + 8) * 2048 + col) =
                make_float2(acc[j][2], acc[j][3]);
        }

        __threadfence();
        if (tid == 0) {
            int old = atomicAdd(&g_cnt2[t & 1][strip], 1);
            s_last = (old == 7) ? 1 : 0;
        }
        __syncthreads();

        if (s_last) {
            __threadfence();
            const float4* p4 = (const float4*)(partBase
                               + (size_t)(t & 1) * (8 * (size_t)BH));
            const float4* x4 = (const float4*)(Xbase + (size_t)t * BH);
            __nv_bfloat162* oHi = (__nv_bfloat162*)(Hhi + (size_t)t * BH);
            __nv_bfloat162* oLo = (__nv_bfloat162*)(Hlo + (size_t)t * BH);
            __half2* o16 = H16 ? (__half2*)(H16 + (size_t)t * BH) : (__half2*)0;

            for (int u = tid; u < 1024; u += 256) {
                const int m  = u >> 4;
                const int c4 = u & 15;
                const size_t off = (size_t)m * 512 + (size_t)strip * 16 + c4;
                float4 sv = p4[off];
#pragma unroll
                for (int kg = 1; kg < 8; kg++) {
                    float4 p = p4[(size_t)kg * (BH / 4) + off];
                    sv.x += p.x; sv.y += p.y; sv.z += p.z; sv.w += p.w;
                }
                float4 xv = x4[off];
                sv.x = tanhf(sv.x + xv.x); sv.y = tanhf(sv.y + xv.y);
                sv.z = tanhf(sv.z + xv.z); sv.w = tanhf(sv.w + xv.w);

                __nv_bfloat16 hx = __float2bfloat16(sv.x);
                __nv_bfloat16 hy = __float2bfloat16(sv.y);
                __nv_bfloat16 hz = __float2bfloat16(sv.z);
                __nv_bfloat16 hw = __float2bfloat16(sv.w);
                __nv_bfloat162 a; a.x = hx; a.y = hy;
                __nv_bfloat162 b; b.x = hz; b.y = hw;
                oHi[2 * off] = a; oHi[2 * off + 1] = b;
                __nv_bfloat162 la, lb;
                la.x = __float2bfloat16(sv.x - __bfloat162float(hx));
                la.y = __float2bfloat16(sv.y - __bfloat162float(hy));
                lb.x = __float2bfloat16(sv.z - __bfloat162float(hz));
                lb.y = __float2bfloat16(sv.w - __bfloat162float(hw));
                oLo[2 * off] = la; oLo[2 * off + 1] = lb;

                if (o16) {
                    __half2 fa; fa.x = __float2half(sv.x); fa.y = __float2half(sv.y);
                    __half2 fb; fb.x = __float2half(sv.z); fb.y = __float2half(sv.w);
                    o16[2 * off] = fa; o16[2 * off + 1] = fb;
                }
            }
            __threadfence();
            __syncthreads();
            if (tid == 0) {
                g_cnt2[t & 1][strip] = 0;
                atomicExch(&g_flag[strip], t + 1);
            }
        }
    }

    /* self-reset for the next launch / graph replay */
    __threadfence();
    __syncthreads();
    if (tid == 0) {
        int old = atomicAdd(&g_done, 1);
        if (old == 255) {
#pragma unroll
            for (int s = 0; s < 32; s++) g_flag[s] = 0;
            __threadfence();
            g_done = 0;
        }
    }
}

/* ------------------------------------------------------------------ */
__global__ void copy_final_hl(
    const __nv_bfloat162* __restrict__ h0h, const __nv_bfloat162* __restrict__ h0l,
    const __nv_bfloat162* __restrict__ h1h, const __nv_bfloat162* __restrict__ h1l,
    float2* __restrict__ out)
{
    const int i = blockIdx.x * 256 + threadIdx.x;
    if (i >= BH) return;
    const __nv_bfloat162 h = (i < BH / 2) ? h0h[i] : h1h[i - BH / 2];
    const __nv_bfloat162 l = (i < BH / 2) ? h0l[i] : h1l[i - BH / 2];
    float2 v;
    v.x = __bfloat162float(h.x) + __bfloat162float(l.x);
    v.y = __bfloat162float(h.y) + __bfloat162float(l.y);
    out[i] = v;
}

/* ------------------------------------------------------------------ */
extern "C" void kernel_launch(void* const* d_in, const int* in_sizes, int n_in,
                              void* d_out, int out_size)
{
    (void)in_sizes; (void)n_in; (void)out_size;

    const void*  inputs = d_in[0];
    const float* hidden = (const float*)d_in[1];
    const float* emb    = (const float*)d_in[2];
    const float* W0     = (const float*)d_in[3];
    const float* b0     = (const float*)d_in[4];
    const float* W1     = (const float*)d_in[5];
    const float* b1     = (const float*)d_in[6];
    const float* Wout   = (const float*)d_in[7];
    const float* bout   = (const float*)d_in[8];
    float* out = (float*)d_out;

    float *pX0, *pX1, *pPart;
    __nv_bfloat16 *pEh, *pEl, *pW0xh, *pW0xl, *pW0hh, *pW0hl;
    __nv_bfloat16 *pW1xh, *pW1xl, *pW1hh, *pW1hl;
    __nv_bfloat16 *pH0h, *pH0l, *pH1h, *pH1l, *pHIh, *pHIl;
    __half *pWof, *pH1fh;
    cudaGetSymbolAddress((void**)&pX0,   g_X0);
    cudaGetSymbolAddress((void**)&pX1,   g_X1);
    cudaGetSymbolAddress((void**)&pPart, g_part);
    cudaGetSymbolAddress((void**)&pEh,   g_emb_hi);
    cudaGetSymbolAddress((void**)&pEl,   g_emb_lo);
    cudaGetSymbolAddress((void**)&pW0xh, g_w0x_hi);
    cudaGetSymbolAddress((void**)&pW0xl, g_w0x_lo);
    cudaGetSymbolAddress((void**)&pW0hh, g_w0h_hi);
    cudaGetSymbolAddress((void**)&pW0hl, g_w0h_lo);
    cudaGetSymbolAddress((void**)&pW1xh, g_w1x_hi);
    cudaGetSymbolAddress((void**)&pW1xl, g_w1x_lo);
    cudaGetSymbolAddress((void**)&pW1hh, g_w1h_hi);
    cudaGetSymbolAddress((void**)&pW1hl, g_w1h_lo);
    cudaGetSymbolAddress((void**)&pWof,  g_woutf);
    cudaGetSymbolAddress((void**)&pH0h,  g_H0_hi);
    cudaGetSymbolAddress((void**)&pH0l,  g_H0_lo);
    cudaGetSymbolAddress((void**)&pH1h,  g_H1_hi);
    cudaGetSymbolAddress((void**)&pH1l,  g_H1_lo);
    cudaGetSymbolAddress((void**)&pH1fh, g_H1f_hi);
    cudaGetSymbolAddress((void**)&pHIh,  g_hin_hi);
    cudaGetSymbolAddress((void**)&pHIl,  g_hin_lo);

    static int smem_set = 0;
    if (!smem_set) {
        cudaFuncSetAttribute(gemm_mma<0,3>,
                             cudaFuncAttributeMaxDynamicSharedMemorySize, GEMM3_SMEM);
        cudaFuncSetAttribute(gemm_mma<1,1>,
                             cudaFuncAttributeMaxDynamicSharedMemorySize, GEMM1_SMEM);
        cudaFuncSetAttribute(rnn_persist,
                             cudaFuncAttributeMaxDynamicSharedMemorySize, STEP_SMEM);
        smem_set = 1;
    }

    detect_idx_kernel<<<1, 32>>>((const unsigned int*)inputs);

    /* hi/lo conversions */
    {
        long n4;
        n4 = (long)VOCAB * (EMB / 4);
        conv_split<<<(unsigned)((n4 + 255) / 256), 256>>>(
            (const float4*)emb, n4, 9, 9, (__nv_bfloat162*)pEh, (__nv_bfloat162*)pEl);
        n4 = (long)VOCAB * (HID / 4);
        conv_f16hi<<<(unsigned)((n4 + 255) / 256), 256>>>(
            (const float4*)Wout, n4, (__half2*)pWof);
        n4 = (long)HID * (HID / 4);
        conv_split<<<(unsigned)((n4 + 255) / 256), 256>>>(
            (const float4*)W0, n4, 9, 10,
            (__nv_bfloat162*)pW0xh, (__nv_bfloat162*)pW0xl);
        conv_split<<<(unsigned)((n4 + 255) / 256), 256>>>(
            (const float4*)(W0 + 2048), n4, 9, 10,
            (__nv_bfloat162*)pW0hh, (__nv_bfloat162*)pW0hl);
        conv_split<<<(unsigned)((n4 + 255) / 256), 256>>>(
            (const float4*)W1, n4, 9, 10,
            (__nv_bfloat162*)pW1xh, (__nv_bfloat162*)pW1xl);
        conv_split<<<(unsigned)((n4 + 255) / 256), 256>>>(
            (const float4*)(W1 + 2048), n4, 9, 10,
            (__nv_bfloat162*)pW1hh, (__nv_bfloat162*)pW1hl);
        n4 = (long)(2 * BH) / 4;
        conv_split<<<(unsigned)((n4 + 255) / 256), 256>>>(
            (const float4*)hidden, n4, 9, 9,
            (__nv_bfloat162*)pHIh, (__nv_bfloat162*)pHIl);
    }

    /* X0 = emb[inputs] @ W0x^T + b0   (bf16, 3-pass) */
    {
        dim3 g(HID / 128, MB_ / 128);
        gemm_mma<0,3><<<g, 256, GEMM3_SMEM>>>(
            (const uint16_t*)pEh, (const uint16_t*)pEl, inputs,
            (const uint16_t*)pW0xh, (const uint16_t*)pW0xl,
            HID, b0, pX0, HID, HID);
    }

    const dim3 gs(32, 8);

    /* layer-0 recurrence: ONE persistent launch (W resident in smem) */
    rnn_persist<<<gs, 256, STEP_SMEM>>>(
        pHIh, pHIl, pW0hh, pW0hl, pX0, pPart,
        pH0h, pH0l, (__half*)0);

    /* X1 = H0 @ W1x^T + b1   (bf16, 3-pass) */
    {
        dim3 g(HID / 128, MB_ / 128);
        gemm_mma<0,3><<<g, 256, GEMM3_SMEM>>>(
            (const uint16_t*)pH0h, (const uint16_t*)pH0l, (const void*)0,
            (const uint16_t*)pW1xh, (const uint16_t*)pW1xl,
            HID, b1, pX1, HID, HID);
    }

    /* layer-1 recurrence: ONE persistent launch (emits fp16 mirror) */
    rnn_persist<<<gs, 256, STEP_SMEM>>>(
        pHIh + BH, pHIl + BH, pW1hh, pW1hl, pX1, pPart,
        pH1h, pH1l, pH1fh);

    /* logits = H1 @ Wout^T + bout   (fp16, 1-pass, 2 CTAs/SM) */
    {
        dim3 g((VOCAB + 127) / 128, MB_ / 128);
        gemm_mma<1,1><<<g, 256, GEMM1_SMEM>>>(
            (const uint16_t*)pH1fh, (const uint16_t*)0, (const void*)0,
            (const uint16_t*)pWof, (const uint16_t*)0,
            VOCAB, bout, out, VOCAB, VOCAB);
    }

    copy_final_hl<<<(BH + 255) / 256, 256>>>(
        (const __nv_bfloat162*)(pH0h + (size_t)(T_SEQ - 1) * BH),
        (const __nv_bfloat162*)(pH0l + (size_t)(T_SEQ - 1) * BH),
        (const __nv_bfloat162*)(pH1h + (size_t)(T_SEQ - 1) * BH),
        (const __nv_bfloat162*)(pH1l + (size_t)(T_SEQ - 1) * BH),
        (float2*)(out + (size_t)MB_ * VOCAB));
}